// round 12
// baseline (speedup 1.0000x reference)
#include <cuda_runtime.h>
#include <cuda_bf16.h>

#define NB 16
#define NL 1024
#define NH 8
#define MROWS (NB*NL)

// ---------------- scratch ----------------
__device__ __align__(16) __nv_bfloat16 g_Qh[NB*NH*NL*64];
__device__ __align__(16) __nv_bfloat16 g_Ql[NB*NH*NL*64];
__device__ __align__(16) __nv_bfloat16 g_Kh[NB*NH*NL*64];
__device__ __align__(16) __nv_bfloat16 g_Kl[NB*NH*NL*64];
__device__ __align__(16) __nv_bfloat16 g_Vh[NB*NH*NL*64];
__device__ __align__(16) __nv_bfloat16 g_Vl[NB*NH*NL*64];
__device__ __align__(16) __nv_bfloat16 g_Ah[3][MROWS*512];
__device__ __align__(16) __nv_bfloat16 g_Al[3][MROWS*512];
__device__ __align__(16) __nv_bfloat16 g_Wh[4][512*512];
__device__ __align__(16) __nv_bfloat16 g_Wl[4][512*512];
__device__ __align__(16) __nv_bfloat16 g_atth[MROWS*512];
__device__ __align__(16) __nv_bfloat16 g_attl[MROWS*512];
__device__ __align__(16) unsigned g_mbits[NB*NL*32];   // 2MB packed mask bits

// ---------------- helpers ----------------
__device__ __forceinline__ unsigned smem_u32(const void* p) {
    unsigned a;
    asm("{ .reg .u64 t; cvta.to.shared.u64 t, %1; cvt.u32.u64 %0, t; }" : "=r"(a) : "l"(p));
    return a;
}
__device__ __forceinline__ void cp16(unsigned dst, const void* src) {
    asm volatile("cp.async.cg.shared.global [%0], [%1], 16;" :: "r"(dst), "l"(src));
}
__device__ __forceinline__ void ldm4(unsigned& r0, unsigned& r1, unsigned& r2, unsigned& r3, unsigned a) {
    asm volatile("ldmatrix.sync.aligned.m8n8.x4.shared.b16 {%0,%1,%2,%3}, [%4];"
                 : "=r"(r0), "=r"(r1), "=r"(r2), "=r"(r3) : "r"(a));
}
__device__ __forceinline__ void ldm2(unsigned& r0, unsigned& r1, unsigned a) {
    asm volatile("ldmatrix.sync.aligned.m8n8.x2.shared.b16 {%0,%1}, [%2];"
                 : "=r"(r0), "=r"(r1) : "r"(a));
}
__device__ __forceinline__ void ldm4t(unsigned& r0, unsigned& r1, unsigned& r2, unsigned& r3, unsigned a) {
    asm volatile("ldmatrix.sync.aligned.m8n8.x4.trans.shared.b16 {%0,%1,%2,%3}, [%4];"
                 : "=r"(r0), "=r"(r1), "=r"(r2), "=r"(r3) : "r"(a));
}
__device__ __forceinline__ void mma_bf16(float* d, const unsigned* a, unsigned b0, unsigned b1) {
    asm volatile(
        "mma.sync.aligned.m16n8k16.row.col.f32.bf16.bf16.f32 "
        "{%0,%1,%2,%3}, {%4,%5,%6,%7}, {%8,%9}, {%0,%1,%2,%3};"
        : "+f"(d[0]), "+f"(d[1]), "+f"(d[2]), "+f"(d[3])
        : "r"(a[0]), "r"(a[1]), "r"(a[2]), "r"(a[3]), "r"(b0), "r"(b1));
}
__device__ __forceinline__ void split_hl(float y, __nv_bfloat16& h, __nv_bfloat16& l) {
    h = __float2bfloat16(y);
    l = __float2bfloat16(y - __bfloat162float(h));
}
__device__ __forceinline__ void store_hl2(__nv_bfloat16* ph, __nv_bfloat16* pl, float a, float b) {
    __nv_bfloat162 H, L;
    split_hl(a, H.x, L.x);
    split_hl(b, H.y, L.y);
    *(__nv_bfloat162*)ph = H;
    *(__nv_bfloat162*)pl = L;
}
__device__ __forceinline__ unsigned pack_hi(float a, float b) {
    __nv_bfloat162 H; H.x = __float2bfloat16(a); H.y = __float2bfloat16(b);
    return *(unsigned*)&H;
}
__device__ __forceinline__ unsigned pack_lo(float a, float b) {
    __nv_bfloat16 ha = __float2bfloat16(a), hb = __float2bfloat16(b);
    __nv_bfloat162 L;
    L.x = __float2bfloat16(a - __bfloat162float(ha));
    L.y = __float2bfloat16(b - __bfloat162float(hb));
    return *(unsigned*)&L;
}

// ---------------- mask bit-packing: 256MB int32 -> 2MB bits ----------------
__global__ __launch_bounds__(256) void pack_mask_kernel(const int* __restrict__ mask)
{
    int warp = threadIdx.x >> 5, lane = threadIdx.x & 31;
    int row = blockIdx.x * 8 + warp;
    const int* mrow = mask + (size_t)row * 1024;
    #pragma unroll
    for (int j = 0; j < 32; j++) {
        int mv = mrow[j * 32 + lane];
        unsigned w = __ballot_sync(0xffffffffu, mv != 0);
        if (lane == 0) g_mbits[row * 32 + j] = w;
    }
}

// ---------------- fused LN: stats + apply + bf16 hi/lo split ----------------
__global__ __launch_bounds__(256) void ln_fused_kernel(
    const float* __restrict__ q, const float* __restrict__ k, const float* __restrict__ v,
    const float* __restrict__ g1, const float* __restrict__ b1,
    const float* __restrict__ g2, const float* __restrict__ b2,
    const float* __restrict__ g3, const float* __restrict__ b3)
{
    int warp = threadIdx.x >> 5, lane = threadIdx.x & 31;
    int t = blockIdx.y;
    int row = blockIdx.x * 8 + warp;
    const float* x  = (t == 0 ? q  : (t == 1 ? k  : v))  + (size_t)row * 512;
    const float* G  = (t == 0 ? g1 : (t == 1 ? g2 : g3));
    const float* Bt = (t == 0 ? b1 : (t == 1 ? b2 : b3));

    float4 xv[4];
    float s = 0.f, ss = 0.f;
    #pragma unroll
    for (int i = 0; i < 4; i++) {
        xv[i] = ((const float4*)x)[lane + 32 * i];
        s  += xv[i].x + xv[i].y + xv[i].z + xv[i].w;
        ss += xv[i].x*xv[i].x + xv[i].y*xv[i].y + xv[i].z*xv[i].z + xv[i].w*xv[i].w;
    }
    #pragma unroll
    for (int o = 16; o; o >>= 1) {
        s  += __shfl_xor_sync(0xffffffffu, s, o);
        ss += __shfl_xor_sync(0xffffffffu, ss, o);
    }
    float mu = s * (1.f / 512.f);
    float var = ss * (1.f / 512.f) - mu * mu;
    float rs = rsqrtf(var + 1e-5f);

    __nv_bfloat16* ph = g_Ah[t] + (size_t)row * 512;
    __nv_bfloat16* pl = g_Al[t] + (size_t)row * 512;
    #pragma unroll
    for (int i = 0; i < 4; i++) {
        int c4 = lane + 32 * i;
        float4 gv = ((const float4*)G)[c4];
        float4 bv = ((const float4*)Bt)[c4];
        float y[4];
        y[0] = (xv[i].x - mu) * rs * gv.x + bv.x;
        y[1] = (xv[i].y - mu) * rs * gv.y + bv.y;
        y[2] = (xv[i].z - mu) * rs * gv.z + bv.z;
        y[3] = (xv[i].w - mu) * rs * gv.w + bv.w;
        __nv_bfloat16 hh[4], ll[4];
        #pragma unroll
        for (int j = 0; j < 4; j++) split_hl(y[j], hh[j], ll[j]);
        *(uint2*)(ph + c4 * 4) = *(uint2*)hh;
        *(uint2*)(pl + c4 * 4) = *(uint2*)ll;
    }
}

__global__ __launch_bounds__(256) void convert_w_kernel(
    const float* __restrict__ Wq, const float* __restrict__ Wk,
    const float* __restrict__ Wv, const float* __restrict__ Wfc)
{
    int idx = (blockIdx.x * 256 + threadIdx.x) * 4;
    int mat = idx >> 18;
    int off = idx & 262143;
    const float* W = (mat == 0) ? Wq : ((mat == 1) ? Wk : ((mat == 2) ? Wv : Wfc));
    float4 xv = *(const float4*)(W + off);
    float y[4] = {xv.x, xv.y, xv.z, xv.w};
    __nv_bfloat16 hh[4], ll[4];
    #pragma unroll
    for (int j = 0; j < 4; j++) split_hl(y[j], hh[j], ll[j]);
    *(uint2*)(g_Wh[mat] + off) = *(uint2*)hh;
    *(uint2*)(g_Wl[mat] + off) = *(uint2*)ll;
}

// ---------------- mma.sync GEMM (exact R7: BK=32, 4-stage, 512 thr) ----------------
#define STG 32768
#define VOFF_AL 8192
#define VOFF_BH 16384
#define VOFF_BL 24576

__device__ __forceinline__ void load_stage_mma(
    const __nv_bfloat16* __restrict__ Ah, const __nv_bfloat16* __restrict__ Al,
    const __nv_bfloat16* __restrict__ Bh, const __nv_bfloat16* __restrict__ Bl,
    int mr0, int nr0, int kb, unsigned dstb, int tid)
{
    int m = tid >> 2;
    int cc = tid & 3;
    int kc = cc >> 1, c = cc & 1;
    unsigned dst = dstb + kc * 4096 + m * 32 + ((unsigned)(c ^ ((m >> 2) & 1)) << 4);
    size_t ga = (size_t)(mr0 + m) * 512 + kb + kc * 16 + c * 8;
    size_t gb = (size_t)(nr0 + m) * 512 + kb + kc * 16 + c * 8;
    cp16(dst,           Ah + ga);
    cp16(dst + VOFF_AL, Al + ga);
    cp16(dst + VOFF_BH, Bh + gb);
    cp16(dst + VOFF_BL, Bl + gb);
    asm volatile("cp.async.commit_group;");
}

__global__ __launch_bounds__(512, 1) void gemm_mma_kernel(float* __restrict__ c_fc, int mode)
{
    extern __shared__ char smem[];
    unsigned sb = smem_u32(smem);
    int tid = threadIdx.x, wid = tid >> 5, lane = tid & 31;
    int z = blockIdx.z;
    int mr0 = blockIdx.y * 128;
    int nr0 = blockIdx.x * 128;

    const __nv_bfloat16 *Ah, *Al, *Wh, *Wl;
    __nv_bfloat16 *oh = 0, *ol = 0;
    if (mode == 0) {
        Ah = g_Ah[z]; Al = g_Al[z]; Wh = g_Wh[z]; Wl = g_Wl[z];
        oh = (z == 0) ? g_Qh : ((z == 1) ? g_Kh : g_Vh);
        ol = (z == 0) ? g_Ql : ((z == 1) ? g_Kl : g_Vl);
    } else {
        Ah = g_atth; Al = g_attl; Wh = g_Wh[3]; Wl = g_Wl[3];
    }

    int rA = lane & 15, chv = lane >> 4;
    unsigned offT = (unsigned)(rA * 32 + ((chv ^ ((rA >> 2) & 1)) << 4));
    int wm = wid >> 2, wn = wid & 3;

    float acc[2][4][4];
    #pragma unroll
    for (int a = 0; a < 2; a++)
        #pragma unroll
        for (int b = 0; b < 4; b++)
            #pragma unroll
            for (int c = 0; c < 4; c++) acc[a][b][c] = 0.f;

    load_stage_mma(Ah, Al, Wh, Wl, mr0, nr0, 0,  sb,           tid);
    load_stage_mma(Ah, Al, Wh, Wl, mr0, nr0, 32, sb + STG,     tid);
    load_stage_mma(Ah, Al, Wh, Wl, mr0, nr0, 64, sb + 2 * STG, tid);

    #pragma unroll 1
    for (int s = 0; s < 16; s++) {
        asm volatile("cp.async.wait_group 2;");
        __syncthreads();
        unsigned buf = sb + (unsigned)(s & 3) * STG;

        #pragma unroll
        for (int kc = 0; kc < 2; kc++) {
            unsigned abase = buf + kc * 4096;
            unsigned bbase = buf + VOFF_BH + kc * 4096;
            unsigned aH[2][4], bH[2][4];
            #pragma unroll
            for (int mt = 0; mt < 2; mt++)
                ldm4(aH[mt][0], aH[mt][1], aH[mt][2], aH[mt][3],
                     abase + (unsigned)((wm * 32 + mt * 16) * 32) + offT);
            #pragma unroll
            for (int bt = 0; bt < 2; bt++)
                ldm4(bH[bt][0], bH[bt][1], bH[bt][2], bH[bt][3],
                     bbase + (unsigned)((wn * 32 + bt * 16) * 32) + offT);
            #pragma unroll
            for (int mt = 0; mt < 2; mt++)
                #pragma unroll
                for (int nt = 0; nt < 4; nt++)
                    mma_bf16(acc[mt][nt], aH[mt], bH[nt >> 1][nt & 1], bH[nt >> 1][(nt & 1) + 2]);
            {
                unsigned bL[2][4];
                #pragma unroll
                for (int bt = 0; bt < 2; bt++)
                    ldm4(bL[bt][0], bL[bt][1], bL[bt][2], bL[bt][3],
                         bbase + 8192 + (unsigned)((wn * 32 + bt * 16) * 32) + offT);
                #pragma unroll
                for (int mt = 0; mt < 2; mt++)
                    #pragma unroll
                    for (int nt = 0; nt < 4; nt++)
                        mma_bf16(acc[mt][nt], aH[mt], bL[nt >> 1][nt & 1], bL[nt >> 1][(nt & 1) + 2]);
            }
            {
                unsigned aL[2][4];
                #pragma unroll
                for (int mt = 0; mt < 2; mt++)
                    ldm4(aL[mt][0], aL[mt][1], aL[mt][2], aL[mt][3],
                         abase + VOFF_AL + (unsigned)((wm * 32 + mt * 16) * 32) + offT);
                #pragma unroll
                for (int mt = 0; mt < 2; mt++)
                    #pragma unroll
                    for (int nt = 0; nt < 4; nt++)
                        mma_bf16(acc[mt][nt], aL[mt], bH[nt >> 1][nt & 1], bH[nt >> 1][(nt & 1) + 2]);
            }
        }

        if (s + 3 < 16)
            load_stage_mma(Ah, Al, Wh, Wl, mr0, nr0, (s + 3) * 32, sb + (unsigned)((s + 3) & 3) * STG, tid);
        else
            asm volatile("cp.async.commit_group;");
    }

    int gr = lane >> 2, gc = (lane & 3) * 2;
    #pragma unroll
    for (int mt = 0; mt < 2; mt++) {
        #pragma unroll
        for (int nt = 0; nt < 4; nt++) {
            int r0 = mr0 + wm * 32 + mt * 16 + gr;
            int n0 = nr0 + wn * 32 + nt * 8 + gc;
            if (mode == 0) {
                int h = n0 >> 6, d = n0 & 63;
                int r1 = r0 + 8;
                size_t p0 = ((size_t)((r0 >> 10) * 8 + h) << 16) + (size_t)(r0 & 1023) * 64 + d;
                size_t p1 = ((size_t)((r1 >> 10) * 8 + h) << 16) + (size_t)(r1 & 1023) * 64 + d;
                store_hl2(oh + p0, ol + p0, acc[mt][nt][0], acc[mt][nt][1]);
                store_hl2(oh + p1, ol + p1, acc[mt][nt][2], acc[mt][nt][3]);
            } else {
                float* p0 = c_fc + (size_t)r0 * 512 + n0;
                *(float2*)p0 = make_float2(acc[mt][nt][0], acc[mt][nt][1]);
                *(float2*)(p0 + 8 * 512) = make_float2(acc[mt][nt][2], acc[mt][nt][3]);
            }
        }
    }
}

// ---------------- tensor-core fused attention (R9 structure + bitmask softmax) ----------------
#define AKB 131072u
#define ABUF 32768u

__device__ __forceinline__ void load_kt512(unsigned buf, const __nv_bfloat16* Kh,
                                           const __nv_bfloat16* Kl, int it, int tid)
{
    #pragma unroll
    for (int i = 0; i < 4; i++) {
        int idx = i * 512 + tid;
        int ver = idx >> 10, g = idx & 1023;
        int row = g >> 3, cc = g & 7;
        int kc = cc >> 1, ch = cc & 1;
        unsigned dst = buf + ver * 16384 + kc * 4096 + row * 32
                     + ((unsigned)(ch ^ ((row >> 2) & 1)) << 4);
        cp16(dst, (ver ? Kl : Kh) + (size_t)(it * 128 + row) * 64 + cc * 8);
    }
    asm volatile("cp.async.commit_group;");
}
__device__ __forceinline__ void load_vt512(unsigned buf, const __nv_bfloat16* Vh,
                                           const __nv_bfloat16* Vl, int it, int tid)
{
    #pragma unroll
    for (int i = 0; i < 4; i++) {
        int idx = i * 512 + tid;
        int ver = idx >> 10, g = idx & 1023;
        int row = g >> 3, cc = g & 7;
        unsigned dst = buf + ver * 16384 + row * 128 + ((unsigned)(cc ^ (row & 7)) << 4);
        cp16(dst, (ver ? Vl : Vh) + (size_t)(it * 128 + row) * 64 + cc * 8);
    }
    asm volatile("cp.async.commit_group;");
}

__global__ __launch_bounds__(512, 1) void attn_mma_kernel(
    const int* __restrict__ mask, float* __restrict__ attn_out)
{
    (void)mask;
    extern __shared__ char smc[];
    unsigned sb = smem_u32(smc);
    float* Ssc = (float*)smc;
    int tid = threadIdx.x, wid = tid >> 5, lane = tid & 31;
    int rA = lane & 15, chv = lane >> 4;
    int gr = lane >> 2, gc = (lane & 3) * 2;
    int q0 = blockIdx.x * 32;
    int bh = blockIdx.y;
    int b = bh >> 3, h = bh & 7;
    const __nv_bfloat16* Qhp = g_Qh + ((size_t)bh << 16) + (size_t)q0 * 64;
    const __nv_bfloat16* Qlp = g_Ql + ((size_t)bh << 16) + (size_t)q0 * 64;
    const __nv_bfloat16* Khp = g_Kh + ((size_t)bh << 16);
    const __nv_bfloat16* Klp = g_Kl + ((size_t)bh << 16);
    const __nv_bfloat16* Vhp = g_Vh + ((size_t)bh << 16);
    const __nv_bfloat16* Vlp = g_Vl + ((size_t)bh << 16);
    unsigned ring = sb + AKB;
    unsigned qarea = ring + 2 * ABUF;   // Q rides in buffer 2, consumed at it=0

    {
        int ver = tid >> 8, rest = tid & 255;
        int row = rest >> 3, cc = rest & 7;
        int kc = cc >> 1, ch = cc & 1;
        unsigned dst = qarea + ver * 4096 + kc * 1024 + row * 32
                     + ((unsigned)(ch ^ ((row >> 2) & 1)) << 4);
        cp16(dst, (ver ? Qlp : Qhp) + row * 64 + cc * 8);
    }
    load_kt512(ring, Khp, Klp, 0, tid);
    load_kt512(ring + ABUF, Khp, Klp, 1, tid);

    unsigned qf[2][4][2][4];
    int n0 = wid * 8;
    unsigned offAq[2];
    #pragma unroll
    for (int mt = 0; mt < 2; mt++) {
        int r = mt * 16 + rA;
        offAq[mt] = r * 32 + ((unsigned)(chv ^ ((r >> 2) & 1)) << 4);
    }
    int rB = n0 + (lane & 7);
    int chB = (lane >> 3) & 1;
    unsigned offB = rB * 32 + ((unsigned)(chB ^ ((rB >> 2) & 1)) << 4);

    // ---- pass 1: S = Q K^T / 8 ----
    #pragma unroll 1
    for (int it = 0; it < 8; it++) {
        asm volatile("cp.async.wait_group 1;" ::: "memory");
        __syncthreads();
        if (it == 0) {
            #pragma unroll
            for (int v = 0; v < 2; v++)
                #pragma unroll
                for (int kc = 0; kc < 4; kc++)
                    #pragma unroll
                    for (int mt = 0; mt < 2; mt++)
                        ldm4(qf[v][kc][mt][0], qf[v][kc][mt][1], qf[v][kc][mt][2], qf[v][kc][mt][3],
                             qarea + v * 4096 + kc * 1024 + offAq[mt]);
            __syncthreads();
        }
        if (it + 2 < 8) load_kt512(ring + (unsigned)((it + 2) % 3) * ABUF, Khp, Klp, it + 2, tid);
        else asm volatile("cp.async.commit_group;");

        unsigned buf = ring + (unsigned)(it % 3) * ABUF;
        float acc[2][4];
        #pragma unroll
        for (int a = 0; a < 2; a++)
            #pragma unroll
            for (int e = 0; e < 4; e++) acc[a][e] = 0.f;
        #pragma unroll
        for (int kc = 0; kc < 4; kc++) {
            unsigned b0h, b1h, b0l, b1l;
            ldm2(b0h, b1h, buf + kc * 4096 + offB);
            ldm2(b0l, b1l, buf + 16384 + kc * 4096 + offB);
            #pragma unroll
            for (int mt = 0; mt < 2; mt++) {
                mma_bf16(acc[mt], qf[0][kc][mt], b0h, b1h);
                mma_bf16(acc[mt], qf[0][kc][mt], b0l, b1l);
                mma_bf16(acc[mt], qf[1][kc][mt], b0h, b1h);
            }
        }
        #pragma unroll
        for (int mt = 0; mt < 2; mt++) {
            int r = mt * 16 + gr;
            int c = it * 128 + n0 + gc;
            unsigned pc0 = (unsigned)c ^ ((unsigned)(r & 7) << 2);
            unsigned pc1 = (unsigned)c ^ ((unsigned)((r + 8) & 7) << 2);
            *(float2*)&Ssc[r * 1024 + pc0] = make_float2(acc[mt][0] * 0.125f, acc[mt][1] * 0.125f);
            *(float2*)&Ssc[(r + 8) * 1024 + pc1] = make_float2(acc[mt][2] * 0.125f, acc[mt][3] * 0.125f);
        }
    }

    load_vt512(ring, Vhp, Vlp, 0, tid);
    __syncthreads();
    load_vt512(ring + ABUF, Vhp, Vlp, 1, tid);

    // ---- register-resident masked softmax (bitmask) + attn write + fused S->P ----
    #pragma unroll 1
    for (int rr = 0; rr < 2; rr++) {
        int r = wid * 2 + rr;
        int qg = q0 + r;
        unsigned xr = (unsigned)(r & 7) << 2;
        const unsigned* mb = g_mbits + (size_t)(b * 1024 + qg) * 32;
        float* srow = &Ssc[r * 1024];

        // masked count from popcount (exact): cnt = popc(all bits) + (diag bit set ? 0 : 1)
        unsigned wl = mb[lane];
        int pc = __popc(wl);
        #pragma unroll
        for (int o = 16; o; o >>= 1) pc += __shfl_xor_sync(0xffffffffu, pc, o);
        unsigned wdiag = __shfl_sync(0xffffffffu, wl, qg >> 5);
        int cnt = pc + (((wdiag >> (qg & 31)) & 1u) ? 0 : 1);

        float treg[32];
        float mx = 0.f;
        unsigned bp = ((unsigned)lane * 2) & 31;
        #pragma unroll
        for (int i = 0; i < 16; i++) {
            int kk = lane * 2 + 64 * i;
            float2 s = *(float2*)&srow[(unsigned)kk ^ xr];
            unsigned w = mb[(lane >> 4) + 2 * i];
            bool a0 = (kk != qg) && !((w >> bp) & 1u);
            bool a1 = (kk + 1 != qg) && !((w >> (bp + 1)) & 1u);
            float t0 = a0 ? s.x : 0.f;
            float t1 = a1 ? s.y : 0.f;
            treg[2 * i] = t0; treg[2 * i + 1] = t1;
            mx = fmaxf(mx, fmaxf(t0, t1));
        }
        #pragma unroll
        for (int o = 16; o; o >>= 1)
            mx = fmaxf(mx, __shfl_xor_sync(0xffffffffu, mx, o));
        float sum = 0.f;
        #pragma unroll
        for (int j = 0; j < 32; j++) {
            float e = (treg[j] != 0.f) ? __expf(treg[j] - mx) : 0.f;
            treg[j] = e;
            sum += e;
        }
        #pragma unroll
        for (int o = 16; o; o >>= 1) sum += __shfl_xor_sync(0xffffffffu, sum, o);
        float Z = sum + (float)cnt * __expf(-mx);
        float inv = 1.f / (sum + 1e-13f * Z);
        float* orow = attn_out + (((size_t)h * NB + b) * 1024 + qg) * 1024;
        #pragma unroll
        for (int i = 0; i < 16; i++) {
            int kk = lane * 2 + 64 * i;
            float a0 = treg[2 * i] * inv, a1 = treg[2 * i + 1] * inv;
            *(float2*)&orow[kk] = make_float2(a0, a1);
            unsigned slot = (unsigned)((kk >> 3) ^ (r & 7));
            unsigned word = ((unsigned)kk >> 1) & 3;
            *(unsigned*)(smc + (size_t)r * 4096 + (slot << 4) + word * 4) = pack_hi(a0, a1);
            *(unsigned*)(smc + (size_t)r * 4096 + (slot << 4) + word * 4 + 2048) = pack_lo(a0, a1);
        }
    }
    __syncthreads();

    // ---- pass 2: out = P V (R9 split: wk4 x wn4) ----
    float pacc[2][2][4];
    #pragma unroll
    for (int a = 0; a < 2; a++)
        #pragma unroll
        for (int c = 0; c < 2; c++)
            #pragma unroll
            for (int e = 0; e < 4; e++) pacc[a][c][e] = 0.f;
    int wk = wid >> 2, wn = wid & 3;

    #pragma unroll 1
    for (int kt = 0; kt < 8; kt++) {
        asm volatile("cp.async.wait_group 1;" ::: "memory");
        __syncthreads();
        if (kt + 2 < 8) load_vt512(ring + (unsigned)((kt + 2) % 3) * ABUF, Vhp, Vlp, kt + 2, tid);
        else asm volatile("cp.async.commit_group;");

        unsigned buf = ring + (unsigned)(kt % 3) * ABUF;
        #pragma unroll
        for (int i = 0; i < 2; i++) {
            int s8 = wk * 2 + i;
            int kseg = kt * 8 + s8;
            unsigned pf[2][2][4];
            #pragma unroll
            for (int v = 0; v < 2; v++)
                #pragma unroll
                for (int mt = 0; mt < 2; mt++) {
                    int r = mt * 16 + rA;
                    unsigned slot = (unsigned)((v * 128 + kseg * 2 + chv) ^ (r & 7));
                    ldm4(pf[v][mt][0], pf[v][mt][1], pf[v][mt][2], pf[v][mt][3],
                         sb + r * 4096 + (slot << 4));
                }
            unsigned bh4[4], bl4[4];
            int krow = s8 * 16 + rA;
            unsigned ob = krow * 128 + ((unsigned)((wn * 2 + chv) ^ (krow & 7)) << 4);
            ldm4t(bh4[0], bh4[1], bh4[2], bh4[3], buf + ob);
            ldm4t(bl4[0], bl4[1], bl4[2], bl4[3], buf + 16384 + ob);
            #pragma unroll
            for (int mt = 0; mt < 2; mt++)
                #pragma unroll
                for (int nt = 0; nt < 2; nt++) {
                    mma_bf16(pacc[mt][nt], pf[0][mt], bh4[nt * 2], bh4[nt * 2 + 1]);
                    mma_bf16(pacc[mt][nt], pf[0][mt], bl4[nt * 2], bl4[nt * 2 + 1]);
                    mma_bf16(pacc[mt][nt], pf[1][mt], bh4[nt * 2], bh4[nt * 2 + 1]);
                }
        }
    }
    asm volatile("cp.async.wait_group 0;" ::: "memory");
    __syncthreads();

    float* red = (float*)(smc + AKB);
    if (wk > 0) {
        int base = (wk - 1) * 2048;
        #pragma unroll
        for (int mt = 0; mt < 2; mt++)
            #pragma unroll
            for (int nt = 0; nt < 2; nt++) {
                int rr0 = mt * 16 + gr;
                int cc0 = wn * 16 + nt * 8 + gc;
                red[base + rr0 * 64 + cc0]     = pacc[mt][nt][0];
                red[base + rr0 * 64 + cc0 + 1] = pacc[mt][nt][1];
                red[base + (rr0 + 8) * 64 + cc0]     = pacc[mt][nt][2];
                red[base + (rr0 + 8) * 64 + cc0 + 1] = pacc[mt][nt][3];
            }
    }
    __syncthreads();
    if (wk == 0) {
        #pragma unroll
        for (int mt = 0; mt < 2; mt++)
            #pragma unroll
            for (int nt = 0; nt < 2; nt++) {
                int rr0 = mt * 16 + gr;
                int cc0 = wn * 16 + nt * 8 + gc;
                float v0 = pacc[mt][nt][0], v1 = pacc[mt][nt][1];
                float v2 = pacc[mt][nt][2], v3 = pacc[mt][nt][3];
                #pragma unroll
                for (int g = 0; g < 3; g++) {
                    v0 += red[g * 2048 + rr0 * 64 + cc0];
                    v1 += red[g * 2048 + rr0 * 64 + cc0 + 1];
                    v2 += red[g * 2048 + (rr0 + 8) * 64 + cc0];
                    v3 += red[g * 2048 + (rr0 + 8) * 64 + cc0 + 1];
                }
                size_t p0 = ((size_t)b * 1024 + q0 + rr0) * 512 + h * 64 + cc0;
                size_t p1 = p0 + 8 * 512;
                store_hl2(&g_atth[p0], &g_attl[p0], v0, v1);
                store_hl2(&g_atth[p1], &g_attl[p1], v2, v3);
            }
    }
}

// ---------------- launch ----------------
extern "C" void kernel_launch(void* const* d_in, const int* in_sizes, int n_in,
                              void* d_out, int out_size)
{
    (void)in_sizes; (void)n_in; (void)out_size;
    const float* q   = (const float*)d_in[0];
    const float* k   = (const float*)d_in[1];
    const float* v   = (const float*)d_in[2];
    const int*   msk = (const int*)d_in[3];
    const float* Wq  = (const float*)d_in[4];
    const float* Wk  = (const float*)d_in[5];
    const float* Wv  = (const float*)d_in[6];
    const float* Wfc = (const float*)d_in[7];
    const float* g1  = (const float*)d_in[8];
    const float* b1  = (const float*)d_in[9];
    const float* g2  = (const float*)d_in[10];
    const float* b2  = (const float*)d_in[11];
    const float* g3  = (const float*)d_in[12];
    const float* b3  = (const float*)d_in[13];

    float* out = (float*)d_out;
    float* dyn_out  = out;                            // [16,1024,512]
    float* attn_out = out + (size_t)MROWS * 512;      // [128,1024,1024]

    const int gemm_smem = 4 * STG;                    // 131072 B
    const int attn_smem = 131072 + 3 * 32768;         // 229376 B
    cudaFuncSetAttribute(gemm_mma_kernel, cudaFuncAttributeMaxDynamicSharedMemorySize, gemm_smem);
    cudaFuncSetAttribute(attn_mma_kernel, cudaFuncAttributeMaxDynamicSharedMemorySize, attn_smem);

    ln_fused_kernel<<<dim3(2048, 3), 256>>>(q, k, v, g1, b1, g2, b2, g3, b3);
    convert_w_kernel<<<1024, 256>>>(Wq, Wk, Wv, Wfc);
    pack_mask_kernel<<<2048, 256>>>(msk);
    gemm_mma_kernel<<<dim3(4, 128, 3), 512, gemm_smem>>>(nullptr, 0);   // Q,K,V projections
    attn_mma_kernel<<<dim3(32, 128), 512, attn_smem>>>(msk, attn_out);
    gemm_mma_kernel<<<dim3(4, 128, 1), 512, gemm_smem>>>(dyn_out, 1);   // fc
}

// round 13
// speedup vs baseline: 1.5233x; 1.5233x over previous
#include <cuda_runtime.h>
#include <cuda_bf16.h>

#define NB 16
#define NL 1024
#define NH 8
#define MROWS (NB*NL)

// ---------------- scratch ----------------
__device__ __align__(16) __nv_bfloat16 g_Qh[NB*NH*NL*64];
__device__ __align__(16) __nv_bfloat16 g_Ql[NB*NH*NL*64];
__device__ __align__(16) __nv_bfloat16 g_Kh[NB*NH*NL*64];
__device__ __align__(16) __nv_bfloat16 g_Kl[NB*NH*NL*64];
__device__ __align__(16) __nv_bfloat16 g_Vh[NB*NH*NL*64];
__device__ __align__(16) __nv_bfloat16 g_Vl[NB*NH*NL*64];
__device__ __align__(16) __nv_bfloat16 g_Ah[3][MROWS*512];
__device__ __align__(16) __nv_bfloat16 g_Al[3][MROWS*512];
__device__ __align__(16) __nv_bfloat16 g_Wh[4][512*512];
__device__ __align__(16) __nv_bfloat16 g_Wl[4][512*512];
__device__ __align__(16) __nv_bfloat16 g_atth[MROWS*512];
__device__ __align__(16) __nv_bfloat16 g_attl[MROWS*512];
__device__ __align__(16) unsigned g_mbits[NB*NL*32];   // 2MB packed mask bits

// ---------------- helpers ----------------
__device__ __forceinline__ unsigned smem_u32(const void* p) {
    unsigned a;
    asm("{ .reg .u64 t; cvta.to.shared.u64 t, %1; cvt.u32.u64 %0, t; }" : "=r"(a) : "l"(p));
    return a;
}
__device__ __forceinline__ void cp16(unsigned dst, const void* src) {
    asm volatile("cp.async.cg.shared.global [%0], [%1], 16;" :: "r"(dst), "l"(src));
}
__device__ __forceinline__ void ldm4(unsigned& r0, unsigned& r1, unsigned& r2, unsigned& r3, unsigned a) {
    asm volatile("ldmatrix.sync.aligned.m8n8.x4.shared.b16 {%0,%1,%2,%3}, [%4];"
                 : "=r"(r0), "=r"(r1), "=r"(r2), "=r"(r3) : "r"(a));
}
__device__ __forceinline__ void ldm2(unsigned& r0, unsigned& r1, unsigned a) {
    asm volatile("ldmatrix.sync.aligned.m8n8.x2.shared.b16 {%0,%1}, [%2];"
                 : "=r"(r0), "=r"(r1) : "r"(a));
}
__device__ __forceinline__ void ldm4t(unsigned& r0, unsigned& r1, unsigned& r2, unsigned& r3, unsigned a) {
    asm volatile("ldmatrix.sync.aligned.m8n8.x4.trans.shared.b16 {%0,%1,%2,%3}, [%4];"
                 : "=r"(r0), "=r"(r1), "=r"(r2), "=r"(r3) : "r"(a));
}
__device__ __forceinline__ void mma_bf16(float* d, const unsigned* a, unsigned b0, unsigned b1) {
    asm volatile(
        "mma.sync.aligned.m16n8k16.row.col.f32.bf16.bf16.f32 "
        "{%0,%1,%2,%3}, {%4,%5,%6,%7}, {%8,%9}, {%0,%1,%2,%3};"
        : "+f"(d[0]), "+f"(d[1]), "+f"(d[2]), "+f"(d[3])
        : "r"(a[0]), "r"(a[1]), "r"(a[2]), "r"(a[3]), "r"(b0), "r"(b1));
}
__device__ __forceinline__ void split_hl(float y, __nv_bfloat16& h, __nv_bfloat16& l) {
    h = __float2bfloat16(y);
    l = __float2bfloat16(y - __bfloat162float(h));
}
__device__ __forceinline__ void store_hl2(__nv_bfloat16* ph, __nv_bfloat16* pl, float a, float b) {
    __nv_bfloat162 H, L;
    split_hl(a, H.x, L.x);
    split_hl(b, H.y, L.y);
    *(__nv_bfloat162*)ph = H;
    *(__nv_bfloat162*)pl = L;
}
__device__ __forceinline__ unsigned pack_hi(float a, float b) {
    __nv_bfloat162 H; H.x = __float2bfloat16(a); H.y = __float2bfloat16(b);
    return *(unsigned*)&H;
}
__device__ __forceinline__ unsigned pack_lo(float a, float b) {
    __nv_bfloat16 ha = __float2bfloat16(a), hb = __float2bfloat16(b);
    __nv_bfloat162 L;
    L.x = __float2bfloat16(a - __bfloat162float(ha));
    L.y = __float2bfloat16(b - __bfloat162float(hb));
    return *(unsigned*)&L;
}

// ---------------- mask bit-packing: 256MB int32 -> 2MB bits ----------------
__global__ __launch_bounds__(256) void pack_mask_kernel(const int* __restrict__ mask)
{
    int warp = threadIdx.x >> 5, lane = threadIdx.x & 31;
    int row = blockIdx.x * 8 + warp;
    const int* mrow = mask + (size_t)row * 1024;
    #pragma unroll
    for (int j = 0; j < 32; j++) {
        int mv = mrow[j * 32 + lane];
        unsigned w = __ballot_sync(0xffffffffu, mv != 0);
        if (lane == 0) g_mbits[row * 32 + j] = w;
    }
}

// ---------------- fused LN: stats + apply + bf16 hi/lo split ----------------
__global__ __launch_bounds__(256) void ln_fused_kernel(
    const float* __restrict__ q, const float* __restrict__ k, const float* __restrict__ v,
    const float* __restrict__ g1, const float* __restrict__ b1,
    const float* __restrict__ g2, const float* __restrict__ b2,
    const float* __restrict__ g3, const float* __restrict__ b3)
{
    int warp = threadIdx.x >> 5, lane = threadIdx.x & 31;
    int t = blockIdx.y;
    int row = blockIdx.x * 8 + warp;
    const float* x  = (t == 0 ? q  : (t == 1 ? k  : v))  + (size_t)row * 512;
    const float* G  = (t == 0 ? g1 : (t == 1 ? g2 : g3));
    const float* Bt = (t == 0 ? b1 : (t == 1 ? b2 : b3));

    float4 xv[4];
    float s = 0.f, ss = 0.f;
    #pragma unroll
    for (int i = 0; i < 4; i++) {
        xv[i] = ((const float4*)x)[lane + 32 * i];
        s  += xv[i].x + xv[i].y + xv[i].z + xv[i].w;
        ss += xv[i].x*xv[i].x + xv[i].y*xv[i].y + xv[i].z*xv[i].z + xv[i].w*xv[i].w;
    }
    #pragma unroll
    for (int o = 16; o; o >>= 1) {
        s  += __shfl_xor_sync(0xffffffffu, s, o);
        ss += __shfl_xor_sync(0xffffffffu, ss, o);
    }
    float mu = s * (1.f / 512.f);
    float var = ss * (1.f / 512.f) - mu * mu;
    float rs = rsqrtf(var + 1e-5f);

    __nv_bfloat16* ph = g_Ah[t] + (size_t)row * 512;
    __nv_bfloat16* pl = g_Al[t] + (size_t)row * 512;
    #pragma unroll
    for (int i = 0; i < 4; i++) {
        int c4 = lane + 32 * i;
        float4 gv = ((const float4*)G)[c4];
        float4 bv = ((const float4*)Bt)[c4];
        float y[4];
        y[0] = (xv[i].x - mu) * rs * gv.x + bv.x;
        y[1] = (xv[i].y - mu) * rs * gv.y + bv.y;
        y[2] = (xv[i].z - mu) * rs * gv.z + bv.z;
        y[3] = (xv[i].w - mu) * rs * gv.w + bv.w;
        __nv_bfloat16 hh[4], ll[4];
        #pragma unroll
        for (int j = 0; j < 4; j++) split_hl(y[j], hh[j], ll[j]);
        *(uint2*)(ph + c4 * 4) = *(uint2*)hh;
        *(uint2*)(pl + c4 * 4) = *(uint2*)ll;
    }
}

__global__ __launch_bounds__(256) void convert_w_kernel(
    const float* __restrict__ Wq, const float* __restrict__ Wk,
    const float* __restrict__ Wv, const float* __restrict__ Wfc)
{
    int idx = (blockIdx.x * 256 + threadIdx.x) * 4;
    int mat = idx >> 18;
    int off = idx & 262143;
    const float* W = (mat == 0) ? Wq : ((mat == 1) ? Wk : ((mat == 2) ? Wv : Wfc));
    float4 xv = *(const float4*)(W + off);
    float y[4] = {xv.x, xv.y, xv.z, xv.w};
    __nv_bfloat16 hh[4], ll[4];
    #pragma unroll
    for (int j = 0; j < 4; j++) split_hl(y[j], hh[j], ll[j]);
    *(uint2*)(g_Wh[mat] + off) = *(uint2*)hh;
    *(uint2*)(g_Wl[mat] + off) = *(uint2*)ll;
}

// ---------------- mma.sync GEMM (exact R7: BK=32, 4-stage, 512 thr) ----------------
#define STG 32768
#define VOFF_AL 8192
#define VOFF_BH 16384
#define VOFF_BL 24576

__device__ __forceinline__ void load_stage_mma(
    const __nv_bfloat16* __restrict__ Ah, const __nv_bfloat16* __restrict__ Al,
    const __nv_bfloat16* __restrict__ Bh, const __nv_bfloat16* __restrict__ Bl,
    int mr0, int nr0, int kb, unsigned dstb, int tid)
{
    int m = tid >> 2;
    int cc = tid & 3;
    int kc = cc >> 1, c = cc & 1;
    unsigned dst = dstb + kc * 4096 + m * 32 + ((unsigned)(c ^ ((m >> 2) & 1)) << 4);
    size_t ga = (size_t)(mr0 + m) * 512 + kb + kc * 16 + c * 8;
    size_t gb = (size_t)(nr0 + m) * 512 + kb + kc * 16 + c * 8;
    cp16(dst,           Ah + ga);
    cp16(dst + VOFF_AL, Al + ga);
    cp16(dst + VOFF_BH, Bh + gb);
    cp16(dst + VOFF_BL, Bl + gb);
    asm volatile("cp.async.commit_group;");
}

__global__ __launch_bounds__(512, 1) void gemm_mma_kernel(float* __restrict__ c_fc, int mode)
{
    extern __shared__ char smem[];
    unsigned sb = smem_u32(smem);
    int tid = threadIdx.x, wid = tid >> 5, lane = tid & 31;
    int z = blockIdx.z;
    int mr0 = blockIdx.y * 128;
    int nr0 = blockIdx.x * 128;

    const __nv_bfloat16 *Ah, *Al, *Wh, *Wl;
    __nv_bfloat16 *oh = 0, *ol = 0;
    if (mode == 0) {
        Ah = g_Ah[z]; Al = g_Al[z]; Wh = g_Wh[z]; Wl = g_Wl[z];
        oh = (z == 0) ? g_Qh : ((z == 1) ? g_Kh : g_Vh);
        ol = (z == 0) ? g_Ql : ((z == 1) ? g_Kl : g_Vl);
    } else {
        Ah = g_atth; Al = g_attl; Wh = g_Wh[3]; Wl = g_Wl[3];
    }

    int rA = lane & 15, chv = lane >> 4;
    unsigned offT = (unsigned)(rA * 32 + ((chv ^ ((rA >> 2) & 1)) << 4));
    int wm = wid >> 2, wn = wid & 3;

    float acc[2][4][4];
    #pragma unroll
    for (int a = 0; a < 2; a++)
        #pragma unroll
        for (int b = 0; b < 4; b++)
            #pragma unroll
            for (int c = 0; c < 4; c++) acc[a][b][c] = 0.f;

    load_stage_mma(Ah, Al, Wh, Wl, mr0, nr0, 0,  sb,           tid);
    load_stage_mma(Ah, Al, Wh, Wl, mr0, nr0, 32, sb + STG,     tid);
    load_stage_mma(Ah, Al, Wh, Wl, mr0, nr0, 64, sb + 2 * STG, tid);

    #pragma unroll 1
    for (int s = 0; s < 16; s++) {
        asm volatile("cp.async.wait_group 2;");
        __syncthreads();
        unsigned buf = sb + (unsigned)(s & 3) * STG;

        #pragma unroll
        for (int kc = 0; kc < 2; kc++) {
            unsigned abase = buf + kc * 4096;
            unsigned bbase = buf + VOFF_BH + kc * 4096;
            unsigned aH[2][4], bH[2][4];
            #pragma unroll
            for (int mt = 0; mt < 2; mt++)
                ldm4(aH[mt][0], aH[mt][1], aH[mt][2], aH[mt][3],
                     abase + (unsigned)((wm * 32 + mt * 16) * 32) + offT);
            #pragma unroll
            for (int bt = 0; bt < 2; bt++)
                ldm4(bH[bt][0], bH[bt][1], bH[bt][2], bH[bt][3],
                     bbase + (unsigned)((wn * 32 + bt * 16) * 32) + offT);
            #pragma unroll
            for (int mt = 0; mt < 2; mt++)
                #pragma unroll
                for (int nt = 0; nt < 4; nt++)
                    mma_bf16(acc[mt][nt], aH[mt], bH[nt >> 1][nt & 1], bH[nt >> 1][(nt & 1) + 2]);
            {
                unsigned bL[2][4];
                #pragma unroll
                for (int bt = 0; bt < 2; bt++)
                    ldm4(bL[bt][0], bL[bt][1], bL[bt][2], bL[bt][3],
                         bbase + 8192 + (unsigned)((wn * 32 + bt * 16) * 32) + offT);
                #pragma unroll
                for (int mt = 0; mt < 2; mt++)
                    #pragma unroll
                    for (int nt = 0; nt < 4; nt++)
                        mma_bf16(acc[mt][nt], aH[mt], bL[nt >> 1][nt & 1], bL[nt >> 1][(nt & 1) + 2]);
            }
            {
                unsigned aL[2][4];
                #pragma unroll
                for (int mt = 0; mt < 2; mt++)
                    ldm4(aL[mt][0], aL[mt][1], aL[mt][2], aL[mt][3],
                         abase + VOFF_AL + (unsigned)((wm * 32 + mt * 16) * 32) + offT);
                #pragma unroll
                for (int mt = 0; mt < 2; mt++)
                    #pragma unroll
                    for (int nt = 0; nt < 4; nt++)
                        mma_bf16(acc[mt][nt], aL[mt], bH[nt >> 1][nt & 1], bH[nt >> 1][(nt & 1) + 2]);
            }
        }

        if (s + 3 < 16)
            load_stage_mma(Ah, Al, Wh, Wl, mr0, nr0, (s + 3) * 32, sb + (unsigned)((s + 3) & 3) * STG, tid);
        else
            asm volatile("cp.async.commit_group;");
    }

    int gr = lane >> 2, gc = (lane & 3) * 2;
    #pragma unroll
    for (int mt = 0; mt < 2; mt++) {
        #pragma unroll
        for (int nt = 0; nt < 4; nt++) {
            int r0 = mr0 + wm * 32 + mt * 16 + gr;
            int n0 = nr0 + wn * 32 + nt * 8 + gc;
            if (mode == 0) {
                int h = n0 >> 6, d = n0 & 63;
                int r1 = r0 + 8;
                size_t p0 = ((size_t)((r0 >> 10) * 8 + h) << 16) + (size_t)(r0 & 1023) * 64 + d;
                size_t p1 = ((size_t)((r1 >> 10) * 8 + h) << 16) + (size_t)(r1 & 1023) * 64 + d;
                store_hl2(oh + p0, ol + p0, acc[mt][nt][0], acc[mt][nt][1]);
                store_hl2(oh + p1, ol + p1, acc[mt][nt][2], acc[mt][nt][3]);
            } else {
                float* p0 = c_fc + (size_t)r0 * 512 + n0;
                *(float2*)p0 = make_float2(acc[mt][nt][0], acc[mt][nt][1]);
                *(float2*)(p0 + 8 * 512) = make_float2(acc[mt][nt][2], acc[mt][nt][3]);
            }
        }
    }
}

// ---------------- tensor-core fused attention (R9 structure + bitmask softmax) ----------------
#define AKB 131072u
#define ABUF 32768u

__device__ __forceinline__ void load_kt512(unsigned buf, const __nv_bfloat16* Kh,
                                           const __nv_bfloat16* Kl, int it, int tid)
{
    #pragma unroll
    for (int i = 0; i < 4; i++) {
        int idx = i * 512 + tid;
        int ver = idx >> 10, g = idx & 1023;
        int row = g >> 3, cc = g & 7;
        int kc = cc >> 1, ch = cc & 1;
        unsigned dst = buf + ver * 16384 + kc * 4096 + row * 32
                     + ((unsigned)(ch ^ ((row >> 2) & 1)) << 4);
        cp16(dst, (ver ? Kl : Kh) + (size_t)(it * 128 + row) * 64 + cc * 8);
    }
    asm volatile("cp.async.commit_group;");
}
__device__ __forceinline__ void load_vt512(unsigned buf, const __nv_bfloat16* Vh,
                                           const __nv_bfloat16* Vl, int it, int tid)
{
    #pragma unroll
    for (int i = 0; i < 4; i++) {
        int idx = i * 512 + tid;
        int ver = idx >> 10, g = idx & 1023;
        int row = g >> 3, cc = g & 7;
        unsigned dst = buf + ver * 16384 + row * 128 + ((unsigned)(cc ^ (row & 7)) << 4);
        cp16(dst, (ver ? Vl : Vh) + (size_t)(it * 128 + row) * 64 + cc * 8);
    }
    asm volatile("cp.async.commit_group;");
}

__global__ __launch_bounds__(512, 1) void attn_mma_kernel(
    const int* __restrict__ mask, float* __restrict__ attn_out)
{
    (void)mask;
    extern __shared__ char smc[];
    unsigned sb = smem_u32(smc);
    float* Ssc = (float*)smc;
    int tid = threadIdx.x, wid = tid >> 5, lane = tid & 31;
    int rA = lane & 15, chv = lane >> 4;
    int gr = lane >> 2, gc = (lane & 3) * 2;
    int q0 = blockIdx.x * 32;
    int bh = blockIdx.y;
    int b = bh >> 3, h = bh & 7;
    const __nv_bfloat16* Qhp = g_Qh + ((size_t)bh << 16) + (size_t)q0 * 64;
    const __nv_bfloat16* Qlp = g_Ql + ((size_t)bh << 16) + (size_t)q0 * 64;
    const __nv_bfloat16* Khp = g_Kh + ((size_t)bh << 16);
    const __nv_bfloat16* Klp = g_Kl + ((size_t)bh << 16);
    const __nv_bfloat16* Vhp = g_Vh + ((size_t)bh << 16);
    const __nv_bfloat16* Vlp = g_Vl + ((size_t)bh << 16);
    unsigned ring = sb + AKB;
    unsigned qarea = ring + 2 * ABUF;   // Q rides in buffer 2, consumed at it=0

    {
        int ver = tid >> 8, rest = tid & 255;
        int row = rest >> 3, cc = rest & 7;
        int kc = cc >> 1, ch = cc & 1;
        unsigned dst = qarea + ver * 4096 + kc * 1024 + row * 32
                     + ((unsigned)(ch ^ ((row >> 2) & 1)) << 4);
        cp16(dst, (ver ? Qlp : Qhp) + row * 64 + cc * 8);
    }
    load_kt512(ring, Khp, Klp, 0, tid);
    load_kt512(ring + ABUF, Khp, Klp, 1, tid);

    unsigned qf[2][4][2][4];
    int n0 = wid * 8;
    unsigned offAq[2];
    #pragma unroll
    for (int mt = 0; mt < 2; mt++) {
        int r = mt * 16 + rA;
        offAq[mt] = r * 32 + ((unsigned)(chv ^ ((r >> 2) & 1)) << 4);
    }
    int rB = n0 + (lane & 7);
    int chB = (lane >> 3) & 1;
    unsigned offB = rB * 32 + ((unsigned)(chB ^ ((rB >> 2) & 1)) << 4);

    // ---- pass 1: S = Q K^T / 8 ----
    #pragma unroll 1
    for (int it = 0; it < 8; it++) {
        asm volatile("cp.async.wait_group 1;" ::: "memory");
        __syncthreads();
        if (it == 0) {
            #pragma unroll
            for (int v = 0; v < 2; v++)
                #pragma unroll
                for (int kc = 0; kc < 4; kc++)
                    #pragma unroll
                    for (int mt = 0; mt < 2; mt++)
                        ldm4(qf[v][kc][mt][0], qf[v][kc][mt][1], qf[v][kc][mt][2], qf[v][kc][mt][3],
                             qarea + v * 4096 + kc * 1024 + offAq[mt]);
            __syncthreads();
        }
        if (it + 2 < 8) load_kt512(ring + (unsigned)((it + 2) % 3) * ABUF, Khp, Klp, it + 2, tid);
        else asm volatile("cp.async.commit_group;");

        unsigned buf = ring + (unsigned)(it % 3) * ABUF;
        float acc[2][4];
        #pragma unroll
        for (int a = 0; a < 2; a++)
            #pragma unroll
            for (int e = 0; e < 4; e++) acc[a][e] = 0.f;
        #pragma unroll
        for (int kc = 0; kc < 4; kc++) {
            unsigned b0h, b1h, b0l, b1l;
            ldm2(b0h, b1h, buf + kc * 4096 + offB);
            ldm2(b0l, b1l, buf + 16384 + kc * 4096 + offB);
            #pragma unroll
            for (int mt = 0; mt < 2; mt++) {
                mma_bf16(acc[mt], qf[0][kc][mt], b0h, b1h);
                mma_bf16(acc[mt], qf[0][kc][mt], b0l, b1l);
                mma_bf16(acc[mt], qf[1][kc][mt], b0h, b1h);
            }
        }
        #pragma unroll
        for (int mt = 0; mt < 2; mt++) {
            int r = mt * 16 + gr;
            int c = it * 128 + n0 + gc;
            unsigned pc0 = (unsigned)c ^ ((unsigned)(r & 7) << 2);
            unsigned pc1 = (unsigned)c ^ ((unsigned)((r + 8) & 7) << 2);
            *(float2*)&Ssc[r * 1024 + pc0] = make_float2(acc[mt][0] * 0.125f, acc[mt][1] * 0.125f);
            *(float2*)&Ssc[(r + 8) * 1024 + pc1] = make_float2(acc[mt][2] * 0.125f, acc[mt][3] * 0.125f);
        }
    }

    load_vt512(ring, Vhp, Vlp, 0, tid);
    __syncthreads();
    load_vt512(ring + ABUF, Vhp, Vlp, 1, tid);

    // ---- register-resident masked softmax (bitmask, hoisted loads) + fused S->P ----
    #pragma unroll 1
    for (int rr = 0; rr < 2; rr++) {
        int r = wid * 2 + rr;
        int qg = q0 + r;
        unsigned xr = (unsigned)(r & 7) << 2;
        const unsigned* mb = g_mbits + (size_t)(b * 1024 + qg) * 32;
        float* srow = &Ssc[r * 1024];

        // hoisted mask word loads (MLP=16)
        unsigned wv[16];
        #pragma unroll
        for (int i = 0; i < 16; i++) wv[i] = __ldg(&mb[(lane >> 4) + 2 * i]);

        // masked count via popcount
        unsigned wl = __ldg(&mb[lane]);
        int pc = __popc(wl);
        #pragma unroll
        for (int o = 16; o; o >>= 1) pc += __shfl_xor_sync(0xffffffffu, pc, o);
        unsigned wdiag = __shfl_sync(0xffffffffu, wl, qg >> 5);
        int cnt = pc + (((wdiag >> (qg & 31)) & 1u) ? 0 : 1);

        float treg[32];
        float mx = 0.f;
        unsigned bp = ((unsigned)lane * 2) & 31;
        #pragma unroll
        for (int i = 0; i < 16; i++) {
            int kk = lane * 2 + 64 * i;
            float2 s = *(float2*)&srow[(unsigned)kk ^ xr];
            bool a0 = (kk != qg) && !((wv[i] >> bp) & 1u);
            bool a1 = (kk + 1 != qg) && !((wv[i] >> (bp + 1)) & 1u);
            float t0 = a0 ? s.x : 0.f;
            float t1 = a1 ? s.y : 0.f;
            treg[2 * i] = t0; treg[2 * i + 1] = t1;
            mx = fmaxf(mx, fmaxf(t0, t1));
        }
        #pragma unroll
        for (int o = 16; o; o >>= 1)
            mx = fmaxf(mx, __shfl_xor_sync(0xffffffffu, mx, o));
        float sum = 0.f;
        #pragma unroll
        for (int j = 0; j < 32; j++) {
            float e = (treg[j] != 0.f) ? __expf(treg[j] - mx) : 0.f;
            treg[j] = e;
            sum += e;
        }
        #pragma unroll
        for (int o = 16; o; o >>= 1) sum += __shfl_xor_sync(0xffffffffu, sum, o);
        float Z = sum + (float)cnt * __expf(-mx);
        float inv = 1.f / (sum + 1e-13f * Z);
        float* orow = attn_out + (((size_t)h * NB + b) * 1024 + qg) * 1024;
        #pragma unroll
        for (int i = 0; i < 16; i++) {
            int kk = lane * 2 + 64 * i;
            float a0 = treg[2 * i] * inv, a1 = treg[2 * i + 1] * inv;
            *(float2*)&orow[kk] = make_float2(a0, a1);
            unsigned slot = (unsigned)((kk >> 3) ^ (r & 7));
            unsigned word = ((unsigned)kk >> 1) & 3;
            *(unsigned*)(smc + (size_t)r * 4096 + (slot << 4) + word * 4) = pack_hi(a0, a1);
            *(unsigned*)(smc + (size_t)r * 4096 + (slot << 4) + word * 4 + 2048) = pack_lo(a0, a1);
        }
    }
    __syncthreads();

    // ---- pass 2: out = P V (R9 split: wk4 x wn4) ----
    float pacc[2][2][4];
    #pragma unroll
    for (int a = 0; a < 2; a++)
        #pragma unroll
        for (int c = 0; c < 2; c++)
            #pragma unroll
            for (int e = 0; e < 4; e++) pacc[a][c][e] = 0.f;
    int wk = wid >> 2, wn = wid & 3;

    #pragma unroll 1
    for (int kt = 0; kt < 8; kt++) {
        asm volatile("cp.async.wait_group 1;" ::: "memory");
        __syncthreads();
        if (kt + 2 < 8) load_vt512(ring + (unsigned)((kt + 2) % 3) * ABUF, Vhp, Vlp, kt + 2, tid);
        else asm volatile("cp.async.commit_group;");

        unsigned buf = ring + (unsigned)(kt % 3) * ABUF;
        #pragma unroll
        for (int i = 0; i < 2; i++) {
            int s8 = wk * 2 + i;
            int kseg = kt * 8 + s8;
            unsigned pf[2][2][4];
            #pragma unroll
            for (int v = 0; v < 2; v++)
                #pragma unroll
                for (int mt = 0; mt < 2; mt++) {
                    int r = mt * 16 + rA;
                    unsigned slot = (unsigned)((v * 128 + kseg * 2 + chv) ^ (r & 7));
                    ldm4(pf[v][mt][0], pf[v][mt][1], pf[v][mt][2], pf[v][mt][3],
                         sb + r * 4096 + (slot << 4));
                }
            unsigned bh4[4], bl4[4];
            int krow = s8 * 16 + rA;
            unsigned ob = krow * 128 + ((unsigned)((wn * 2 + chv) ^ (krow & 7)) << 4);
            ldm4t(bh4[0], bh4[1], bh4[2], bh4[3], buf + ob);
            ldm4t(bl4[0], bl4[1], bl4[2], bl4[3], buf + 16384 + ob);
            #pragma unroll
            for (int mt = 0; mt < 2; mt++)
                #pragma unroll
                for (int nt = 0; nt < 2; nt++) {
                    mma_bf16(pacc[mt][nt], pf[0][mt], bh4[nt * 2], bh4[nt * 2 + 1]);
                    mma_bf16(pacc[mt][nt], pf[0][mt], bl4[nt * 2], bl4[nt * 2 + 1]);
                    mma_bf16(pacc[mt][nt], pf[1][mt], bh4[nt * 2], bh4[nt * 2 + 1]);
                }
        }
    }
    asm volatile("cp.async.wait_group 0;" ::: "memory");
    __syncthreads();

    float* red = (float*)(smc + AKB);
    if (wk > 0) {
        int base = (wk - 1) * 2048;
        #pragma unroll
        for (int mt = 0; mt < 2; mt++)
            #pragma unroll
            for (int nt = 0; nt < 2; nt++) {
                int rr0 = mt * 16 + gr;
                int cc0 = wn * 16 + nt * 8 + gc;
                red[base + rr0 * 64 + cc0]     = pacc[mt][nt][0];
                red[base + rr0 * 64 + cc0 + 1] = pacc[mt][nt][1];
                red[base + (rr0 + 8) * 64 + cc0]     = pacc[mt][nt][2];
                red[base + (rr0 + 8) * 64 + cc0 + 1] = pacc[mt][nt][3];
            }
    }
    __syncthreads();
    if (wk == 0) {
        #pragma unroll
        for (int mt = 0; mt < 2; mt++)
            #pragma unroll
            for (int nt = 0; nt < 2; nt++) {
                int rr0 = mt * 16 + gr;
                int cc0 = wn * 16 + nt * 8 + gc;
                float v0 = pacc[mt][nt][0], v1 = pacc[mt][nt][1];
                float v2 = pacc[mt][nt][2], v3 = pacc[mt][nt][3];
                #pragma unroll
                for (int g = 0; g < 3; g++) {
                    v0 += red[g * 2048 + rr0 * 64 + cc0];
                    v1 += red[g * 2048 + rr0 * 64 + cc0 + 1];
                    v2 += red[g * 2048 + (rr0 + 8) * 64 + cc0];
                    v3 += red[g * 2048 + (rr0 + 8) * 64 + cc0 + 1];
                }
                size_t p0 = ((size_t)b * 1024 + q0 + rr0) * 512 + h * 64 + cc0;
                size_t p1 = p0 + 8 * 512;
                store_hl2(&g_atth[p0], &g_attl[p0], v0, v1);
                store_hl2(&g_atth[p1], &g_attl[p1], v2, v3);
            }
    }
}

// ---------------- launch ----------------
extern "C" void kernel_launch(void* const* d_in, const int* in_sizes, int n_in,
                              void* d_out, int out_size)
{
    (void)in_sizes; (void)n_in; (void)out_size;
    const float* q   = (const float*)d_in[0];
    const float* k   = (const float*)d_in[1];
    const float* v   = (const float*)d_in[2];
    const int*   msk = (const int*)d_in[3];
    const float* Wq  = (const float*)d_in[4];
    const float* Wk  = (const float*)d_in[5];
    const float* Wv  = (const float*)d_in[6];
    const float* Wfc = (const float*)d_in[7];
    const float* g1  = (const float*)d_in[8];
    const float* b1  = (const float*)d_in[9];
    const float* g2  = (const float*)d_in[10];
    const float* b2  = (const float*)d_in[11];
    const float* g3  = (const float*)d_in[12];
    const float* b3  = (const float*)d_in[13];

    float* out = (float*)d_out;
    float* dyn_out  = out;                            // [16,1024,512]
    float* attn_out = out + (size_t)MROWS * 512;      // [128,1024,1024]

    const int gemm_smem = 4 * STG;                    // 131072 B
    const int attn_smem = 131072 + 3 * 32768;         // 229376 B
    cudaFuncSetAttribute(gemm_mma_kernel, cudaFuncAttributeMaxDynamicSharedMemorySize, gemm_smem);
    cudaFuncSetAttribute(attn_mma_kernel, cudaFuncAttributeMaxDynamicSharedMemorySize, attn_smem);

    pack_mask_kernel<<<2048, 256>>>(msk);
    ln_fused_kernel<<<dim3(2048, 3), 256>>>(q, k, v, g1, b1, g2, b2, g3, b3);
    convert_w_kernel<<<1024, 256>>>(Wq, Wk, Wv, Wfc);
    gemm_mma_kernel<<<dim3(4, 128, 3), 512, gemm_smem>>>(nullptr, 0);   // Q,K,V projections
    attn_mma_kernel<<<dim3(32, 128), 512, attn_smem>>>(msk, attn_out);
    gemm_mma_kernel<<<dim3(4, 128, 1), 512, gemm_smem>>>(dyn_out, 1);   // fc
}

// round 14
// speedup vs baseline: 1.5346x; 1.0074x over previous
#include <cuda_runtime.h>
#include <cuda_bf16.h>

#define NB 16
#define NL 1024
#define NH 8
#define MROWS (NB*NL)

// ---------------- scratch ----------------
__device__ __align__(16) __nv_bfloat16 g_Qh[NB*NH*NL*64];
__device__ __align__(16) __nv_bfloat16 g_Ql[NB*NH*NL*64];
__device__ __align__(16) __nv_bfloat16 g_Kh[NB*NH*NL*64];
__device__ __align__(16) __nv_bfloat16 g_Kl[NB*NH*NL*64];
__device__ __align__(16) __nv_bfloat16 g_Vh[NB*NH*NL*64];
__device__ __align__(16) __nv_bfloat16 g_Vl[NB*NH*NL*64];
__device__ __align__(16) __nv_bfloat16 g_Ah[3][MROWS*512];
__device__ __align__(16) __nv_bfloat16 g_Al[3][MROWS*512];
__device__ __align__(16) __nv_bfloat16 g_Wh[4][512*512];
__device__ __align__(16) __nv_bfloat16 g_Wl[4][512*512];
__device__ __align__(16) __nv_bfloat16 g_atth[MROWS*512];
__device__ __align__(16) __nv_bfloat16 g_attl[MROWS*512];
__device__ __align__(16) unsigned g_mbits[NB*NL*32];   // 2MB packed mask bits

// ---------------- helpers ----------------
__device__ __forceinline__ unsigned smem_u32(const void* p) {
    unsigned a;
    asm("{ .reg .u64 t; cvta.to.shared.u64 t, %1; cvt.u32.u64 %0, t; }" : "=r"(a) : "l"(p));
    return a;
}
__device__ __forceinline__ void cp16(unsigned dst, const void* src) {
    asm volatile("cp.async.cg.shared.global [%0], [%1], 16;" :: "r"(dst), "l"(src));
}
__device__ __forceinline__ void ldm4(unsigned& r0, unsigned& r1, unsigned& r2, unsigned& r3, unsigned a) {
    asm volatile("ldmatrix.sync.aligned.m8n8.x4.shared.b16 {%0,%1,%2,%3}, [%4];"
                 : "=r"(r0), "=r"(r1), "=r"(r2), "=r"(r3) : "r"(a));
}
__device__ __forceinline__ void ldm2(unsigned& r0, unsigned& r1, unsigned a) {
    asm volatile("ldmatrix.sync.aligned.m8n8.x2.shared.b16 {%0,%1}, [%2];"
                 : "=r"(r0), "=r"(r1) : "r"(a));
}
__device__ __forceinline__ void ldm4t(unsigned& r0, unsigned& r1, unsigned& r2, unsigned& r3, unsigned a) {
    asm volatile("ldmatrix.sync.aligned.m8n8.x4.trans.shared.b16 {%0,%1,%2,%3}, [%4];"
                 : "=r"(r0), "=r"(r1), "=r"(r2), "=r"(r3) : "r"(a));
}
__device__ __forceinline__ void mma_bf16(float* d, const unsigned* a, unsigned b0, unsigned b1) {
    asm volatile(
        "mma.sync.aligned.m16n8k16.row.col.f32.bf16.bf16.f32 "
        "{%0,%1,%2,%3}, {%4,%5,%6,%7}, {%8,%9}, {%0,%1,%2,%3};"
        : "+f"(d[0]), "+f"(d[1]), "+f"(d[2]), "+f"(d[3])
        : "r"(a[0]), "r"(a[1]), "r"(a[2]), "r"(a[3]), "r"(b0), "r"(b1));
}
__device__ __forceinline__ void split_hl(float y, __nv_bfloat16& h, __nv_bfloat16& l) {
    h = __float2bfloat16(y);
    l = __float2bfloat16(y - __bfloat162float(h));
}
__device__ __forceinline__ void store_hl2(__nv_bfloat16* ph, __nv_bfloat16* pl, float a, float b) {
    __nv_bfloat162 H, L;
    split_hl(a, H.x, L.x);
    split_hl(b, H.y, L.y);
    *(__nv_bfloat162*)ph = H;
    *(__nv_bfloat162*)pl = L;
}
__device__ __forceinline__ unsigned pack_hi(float a, float b) {
    __nv_bfloat162 H; H.x = __float2bfloat16(a); H.y = __float2bfloat16(b);
    return *(unsigned*)&H;
}
__device__ __forceinline__ unsigned pack_lo(float a, float b) {
    __nv_bfloat16 ha = __float2bfloat16(a), hb = __float2bfloat16(b);
    __nv_bfloat162 L;
    L.x = __float2bfloat16(a - __bfloat162float(ha));
    L.y = __float2bfloat16(b - __bfloat162float(hb));
    return *(unsigned*)&L;
}

// ---------------- mask bit-packing ----------------
__global__ __launch_bounds__(256) void pack_mask_kernel(const int* __restrict__ mask)
{
    int warp = threadIdx.x >> 5, lane = threadIdx.x & 31;
    int row = blockIdx.x * 8 + warp;
    const int* mrow = mask + (size_t)row * 1024;
    #pragma unroll
    for (int j = 0; j < 32; j++) {
        int mv = mrow[j * 32 + lane];
        unsigned w = __ballot_sync(0xffffffffu, mv != 0);
        if (lane == 0) g_mbits[row * 32 + j] = w;
    }
}

// ---------------- fused LN: stats + apply + bf16 hi/lo split ----------------
__global__ __launch_bounds__(256) void ln_fused_kernel(
    const float* __restrict__ q, const float* __restrict__ k, const float* __restrict__ v,
    const float* __restrict__ g1, const float* __restrict__ b1,
    const float* __restrict__ g2, const float* __restrict__ b2,
    const float* __restrict__ g3, const float* __restrict__ b3)
{
    int warp = threadIdx.x >> 5, lane = threadIdx.x & 31;
    int t = blockIdx.y;
    int row = blockIdx.x * 8 + warp;
    const float* x  = (t == 0 ? q  : (t == 1 ? k  : v))  + (size_t)row * 512;
    const float* G  = (t == 0 ? g1 : (t == 1 ? g2 : g3));
    const float* Bt = (t == 0 ? b1 : (t == 1 ? b2 : b3));

    float4 xv[4];
    float s = 0.f, ss = 0.f;
    #pragma unroll
    for (int i = 0; i < 4; i++) {
        xv[i] = ((const float4*)x)[lane + 32 * i];
        s  += xv[i].x + xv[i].y + xv[i].z + xv[i].w;
        ss += xv[i].x*xv[i].x + xv[i].y*xv[i].y + xv[i].z*xv[i].z + xv[i].w*xv[i].w;
    }
    #pragma unroll
    for (int o = 16; o; o >>= 1) {
        s  += __shfl_xor_sync(0xffffffffu, s, o);
        ss += __shfl_xor_sync(0xffffffffu, ss, o);
    }
    float mu = s * (1.f / 512.f);
    float var = ss * (1.f / 512.f) - mu * mu;
    float rs = rsqrtf(var + 1e-5f);

    __nv_bfloat16* ph = g_Ah[t] + (size_t)row * 512;
    __nv_bfloat16* pl = g_Al[t] + (size_t)row * 512;
    #pragma unroll
    for (int i = 0; i < 4; i++) {
        int c4 = lane + 32 * i;
        float4 gv = ((const float4*)G)[c4];
        float4 bv = ((const float4*)Bt)[c4];
        float y[4];
        y[0] = (xv[i].x - mu) * rs * gv.x + bv.x;
        y[1] = (xv[i].y - mu) * rs * gv.y + bv.y;
        y[2] = (xv[i].z - mu) * rs * gv.z + bv.z;
        y[3] = (xv[i].w - mu) * rs * gv.w + bv.w;
        __nv_bfloat16 hh[4], ll[4];
        #pragma unroll
        for (int j = 0; j < 4; j++) split_hl(y[j], hh[j], ll[j]);
        *(uint2*)(ph + c4 * 4) = *(uint2*)hh;
        *(uint2*)(pl + c4 * 4) = *(uint2*)ll;
    }
}

__global__ __launch_bounds__(256) void convert_w_kernel(
    const float* __restrict__ Wq, const float* __restrict__ Wk,
    const float* __restrict__ Wv, const float* __restrict__ Wfc)
{
    int idx = (blockIdx.x * 256 + threadIdx.x) * 4;
    int mat = idx >> 18;
    int off = idx & 262143;
    const float* W = (mat == 0) ? Wq : ((mat == 1) ? Wk : ((mat == 2) ? Wv : Wfc));
    float4 xv = *(const float4*)(W + off);
    float y[4] = {xv.x, xv.y, xv.z, xv.w};
    __nv_bfloat16 hh[4], ll[4];
    #pragma unroll
    for (int j = 0; j < 4; j++) split_hl(y[j], hh[j], ll[j]);
    *(uint2*)(g_Wh[mat] + off) = *(uint2*)hh;
    *(uint2*)(g_Wl[mat] + off) = *(uint2*)ll;
}

// ---------------- mma.sync GEMM: 256 thr, 2 CTA/SM, BM=128 BN=64 BK=32 ----------------
// Stage: Ah 8K | Al 8K | Bh 4K | Bl 4K = 24KB; 4 stages = 96KB -> 2 CTAs/SM.
#define STG 24576
#define VOFF_AL 8192
#define VOFF_BH 16384
#define VOFF_BL 20480

__device__ __forceinline__ void load_stage_mma(
    const __nv_bfloat16* __restrict__ Ah, const __nv_bfloat16* __restrict__ Al,
    const __nv_bfloat16* __restrict__ Bh, const __nv_bfloat16* __restrict__ Bl,
    int mr0, int nr0, int kb, unsigned dstb, int tid)
{
    // A: 128 rows x 32 k (hi+lo): thread -> row=tid>>1, c=tid&1; kc loop
    {
        int m = tid >> 1, c = tid & 1;
        unsigned sw = (unsigned)(c ^ ((m >> 2) & 1)) << 4;
        #pragma unroll
        for (int kc = 0; kc < 2; kc++) {
            unsigned dst = dstb + kc * 4096 + m * 32 + sw;
            size_t ga = (size_t)(mr0 + m) * 512 + kb + kc * 16 + c * 8;
            cp16(dst,           Ah + ga);
            cp16(dst + VOFF_AL, Al + ga);
        }
    }
    // B: 64 rows x 32 k (hi+lo): thread -> row=tid>>2, kc=(tid>>1)&1, c=tid&1
    {
        int m = tid >> 2, kc = (tid >> 1) & 1, c = tid & 1;
        unsigned sw = (unsigned)(c ^ ((m >> 2) & 1)) << 4;
        unsigned dst = dstb + VOFF_BH + kc * 2048 + m * 32 + sw;
        size_t gb = (size_t)(nr0 + m) * 512 + kb + kc * 16 + c * 8;
        cp16(dst,                     Bh + gb);
        cp16(dst + (VOFF_BL - VOFF_BH), Bl + gb);
    }
    asm volatile("cp.async.commit_group;");
}

__global__ __launch_bounds__(256, 2) void gemm_mma_kernel(float* __restrict__ c_fc, int mode)
{
    extern __shared__ char smem[];
    unsigned sb = smem_u32(smem);
    int tid = threadIdx.x, wid = tid >> 5, lane = tid & 31;
    int z = blockIdx.z;
    int mr0 = blockIdx.y * 128;
    int nr0 = blockIdx.x * 64;

    const __nv_bfloat16 *Ah, *Al, *Wh, *Wl;
    __nv_bfloat16 *oh = 0, *ol = 0;
    if (mode == 0) {
        Ah = g_Ah[z]; Al = g_Al[z]; Wh = g_Wh[z]; Wl = g_Wl[z];
        oh = (z == 0) ? g_Qh : ((z == 1) ? g_Kh : g_Vh);
        ol = (z == 0) ? g_Ql : ((z == 1) ? g_Kl : g_Vl);
    } else {
        Ah = g_atth; Al = g_attl; Wh = g_Wh[3]; Wl = g_Wl[3];
    }

    int rA = lane & 15, chv = lane >> 4;
    unsigned offT = (unsigned)(rA * 32 + ((chv ^ ((rA >> 2) & 1)) << 4));
    int wm = wid >> 1, wn = wid & 1;   // warp tile: rows wm*32, cols wn*32

    float acc[2][4][4];
    #pragma unroll
    for (int a = 0; a < 2; a++)
        #pragma unroll
        for (int b = 0; b < 4; b++)
            #pragma unroll
            for (int c = 0; c < 4; c++) acc[a][b][c] = 0.f;

    load_stage_mma(Ah, Al, Wh, Wl, mr0, nr0, 0,  sb,           tid);
    load_stage_mma(Ah, Al, Wh, Wl, mr0, nr0, 32, sb + STG,     tid);
    load_stage_mma(Ah, Al, Wh, Wl, mr0, nr0, 64, sb + 2 * STG, tid);

    #pragma unroll 1
    for (int s = 0; s < 16; s++) {
        if (s < 14) { asm volatile("cp.async.wait_group 2;"); }
        else        { asm volatile("cp.async.wait_group 0;"); }
        __syncthreads();
        // load-before-compute: target buffer (s+3)&3 was consumed at stage s-1,
        // all its ldmatrix reads completed before this barrier.
        if (s + 3 < 16)
            load_stage_mma(Ah, Al, Wh, Wl, mr0, nr0, (s + 3) * 32, sb + (unsigned)((s + 3) & 3) * STG, tid);
        unsigned buf = sb + (unsigned)(s & 3) * STG;

        #pragma unroll
        for (int kc = 0; kc < 2; kc++) {
            unsigned abase  = buf + kc * 4096;
            unsigned bbaseh = buf + VOFF_BH + kc * 2048;
            unsigned bbasel = buf + VOFF_BL + kc * 2048;
            unsigned aH[2][4], bH[2][4];
            #pragma unroll
            for (int mt = 0; mt < 2; mt++)
                ldm4(aH[mt][0], aH[mt][1], aH[mt][2], aH[mt][3],
                     abase + (unsigned)((wm * 32 + mt * 16) * 32) + offT);
            #pragma unroll
            for (int bt = 0; bt < 2; bt++)
                ldm4(bH[bt][0], bH[bt][1], bH[bt][2], bH[bt][3],
                     bbaseh + (unsigned)((wn * 32 + bt * 16) * 32) + offT);
            #pragma unroll
            for (int mt = 0; mt < 2; mt++)
                #pragma unroll
                for (int nt = 0; nt < 4; nt++)
                    mma_bf16(acc[mt][nt], aH[mt], bH[nt >> 1][nt & 1], bH[nt >> 1][(nt & 1) + 2]);
            {
                unsigned bL[2][4];
                #pragma unroll
                for (int bt = 0; bt < 2; bt++)
                    ldm4(bL[bt][0], bL[bt][1], bL[bt][2], bL[bt][3],
                         bbasel + (unsigned)((wn * 32 + bt * 16) * 32) + offT);
                #pragma unroll
                for (int mt = 0; mt < 2; mt++)
                    #pragma unroll
                    for (int nt = 0; nt < 4; nt++)
                        mma_bf16(acc[mt][nt], aH[mt], bL[nt >> 1][nt & 1], bL[nt >> 1][(nt & 1) + 2]);
            }
            {
                unsigned aL[2][4];
                #pragma unroll
                for (int mt = 0; mt < 2; mt++)
                    ldm4(aL[mt][0], aL[mt][1], aL[mt][2], aL[mt][3],
                         abase + VOFF_AL + (unsigned)((wm * 32 + mt * 16) * 32) + offT);
                #pragma unroll
                for (int mt = 0; mt < 2; mt++)
                    #pragma unroll
                    for (int nt = 0; nt < 4; nt++)
                        mma_bf16(acc[mt][nt], aL[mt], bH[nt >> 1][nt & 1], bH[nt >> 1][(nt & 1) + 2]);
            }
        }
    }

    int gr = lane >> 2, gc = (lane & 3) * 2;
    #pragma unroll
    for (int mt = 0; mt < 2; mt++) {
        #pragma unroll
        for (int nt = 0; nt < 4; nt++) {
            int r0 = mr0 + wm * 32 + mt * 16 + gr;
            int n0 = nr0 + wn * 32 + nt * 8 + gc;
            if (mode == 0) {
                int h = n0 >> 6, d = n0 & 63;
                int r1 = r0 + 8;
                size_t p0 = ((size_t)((r0 >> 10) * 8 + h) << 16) + (size_t)(r0 & 1023) * 64 + d;
                size_t p1 = ((size_t)((r1 >> 10) * 8 + h) << 16) + (size_t)(r1 & 1023) * 64 + d;
                store_hl2(oh + p0, ol + p0, acc[mt][nt][0], acc[mt][nt][1]);
                store_hl2(oh + p1, ol + p1, acc[mt][nt][2], acc[mt][nt][3]);
            } else {
                float* p0 = c_fc + (size_t)r0 * 512 + n0;
                *(float2*)p0 = make_float2(acc[mt][nt][0], acc[mt][nt][1]);
                *(float2*)(p0 + 8 * 512) = make_float2(acc[mt][nt][2], acc[mt][nt][3]);
            }
        }
    }
}

// ---------------- tensor-core fused attention (verbatim R12 - validated 1053us) ----------------
#define AKB 131072u
#define ABUF 32768u

__device__ __forceinline__ void load_kt512(unsigned buf, const __nv_bfloat16* Kh,
                                           const __nv_bfloat16* Kl, int it, int tid)
{
    #pragma unroll
    for (int i = 0; i < 4; i++) {
        int idx = i * 512 + tid;
        int ver = idx >> 10, g = idx & 1023;
        int row = g >> 3, cc = g & 7;
        int kc = cc >> 1, ch = cc & 1;
        unsigned dst = buf + ver * 16384 + kc * 4096 + row * 32
                     + ((unsigned)(ch ^ ((row >> 2) & 1)) << 4);
        cp16(dst, (ver ? Kl : Kh) + (size_t)(it * 128 + row) * 64 + cc * 8);
    }
    asm volatile("cp.async.commit_group;");
}
__device__ __forceinline__ void load_vt512(unsigned buf, const __nv_bfloat16* Vh,
                                           const __nv_bfloat16* Vl, int it, int tid)
{
    #pragma unroll
    for (int i = 0; i < 4; i++) {
        int idx = i * 512 + tid;
        int ver = idx >> 10, g = idx & 1023;
        int row = g >> 3, cc = g & 7;
        unsigned dst = buf + ver * 16384 + row * 128 + ((unsigned)(cc ^ (row & 7)) << 4);
        cp16(dst, (ver ? Vl : Vh) + (size_t)(it * 128 + row) * 64 + cc * 8);
    }
    asm volatile("cp.async.commit_group;");
}

__global__ __launch_bounds__(512, 1) void attn_mma_kernel(
    const int* __restrict__ mask, float* __restrict__ attn_out)
{
    (void)mask;
    extern __shared__ char smc[];
    unsigned sb = smem_u32(smc);
    float* Ssc = (float*)smc;
    int tid = threadIdx.x, wid = tid >> 5, lane = tid & 31;
    int rA = lane & 15, chv = lane >> 4;
    int gr = lane >> 2, gc = (lane & 3) * 2;
    int q0 = blockIdx.x * 32;
    int bh = blockIdx.y;
    int b = bh >> 3, h = bh & 7;
    const __nv_bfloat16* Qhp = g_Qh + ((size_t)bh << 16) + (size_t)q0 * 64;
    const __nv_bfloat16* Qlp = g_Ql + ((size_t)bh << 16) + (size_t)q0 * 64;
    const __nv_bfloat16* Khp = g_Kh + ((size_t)bh << 16);
    const __nv_bfloat16* Klp = g_Kl + ((size_t)bh << 16);
    const __nv_bfloat16* Vhp = g_Vh + ((size_t)bh << 16);
    const __nv_bfloat16* Vlp = g_Vl + ((size_t)bh << 16);
    unsigned ring = sb + AKB;
    unsigned qarea = ring + 2 * ABUF;

    {
        int ver = tid >> 8, rest = tid & 255;
        int row = rest >> 3, cc = rest & 7;
        int kc = cc >> 1, ch = cc & 1;
        unsigned dst = qarea + ver * 4096 + kc * 1024 + row * 32
                     + ((unsigned)(ch ^ ((row >> 2) & 1)) << 4);
        cp16(dst, (ver ? Qlp : Qhp) + row * 64 + cc * 8);
    }
    load_kt512(ring, Khp, Klp, 0, tid);
    load_kt512(ring + ABUF, Khp, Klp, 1, tid);

    unsigned qf[2][4][2][4];
    int n0 = wid * 8;
    unsigned offAq[2];
    #pragma unroll
    for (int mt = 0; mt < 2; mt++) {
        int r = mt * 16 + rA;
        offAq[mt] = r * 32 + ((unsigned)(chv ^ ((r >> 2) & 1)) << 4);
    }
    int rB = n0 + (lane & 7);
    int chB = (lane >> 3) & 1;
    unsigned offB = rB * 32 + ((unsigned)(chB ^ ((rB >> 2) & 1)) << 4);

    // ---- pass 1: S = Q K^T / 8 ----
    #pragma unroll 1
    for (int it = 0; it < 8; it++) {
        asm volatile("cp.async.wait_group 1;" ::: "memory");
        __syncthreads();
        if (it == 0) {
            #pragma unroll
            for (int v = 0; v < 2; v++)
                #pragma unroll
                for (int kc = 0; kc < 4; kc++)
                    #pragma unroll
                    for (int mt = 0; mt < 2; mt++)
                        ldm4(qf[v][kc][mt][0], qf[v][kc][mt][1], qf[v][kc][mt][2], qf[v][kc][mt][3],
                             qarea + v * 4096 + kc * 1024 + offAq[mt]);
            __syncthreads();
        }
        if (it + 2 < 8) load_kt512(ring + (unsigned)((it + 2) % 3) * ABUF, Khp, Klp, it + 2, tid);
        else asm volatile("cp.async.commit_group;");

        unsigned buf = ring + (unsigned)(it % 3) * ABUF;
        float acc[2][4];
        #pragma unroll
        for (int a = 0; a < 2; a++)
            #pragma unroll
            for (int e = 0; e < 4; e++) acc[a][e] = 0.f;
        #pragma unroll
        for (int kc = 0; kc < 4; kc++) {
            unsigned b0h, b1h, b0l, b1l;
            ldm2(b0h, b1h, buf + kc * 4096 + offB);
            ldm2(b0l, b1l, buf + 16384 + kc * 4096 + offB);
            #pragma unroll
            for (int mt = 0; mt < 2; mt++) {
                mma_bf16(acc[mt], qf[0][kc][mt], b0h, b1h);
                mma_bf16(acc[mt], qf[0][kc][mt], b0l, b1l);
                mma_bf16(acc[mt], qf[1][kc][mt], b0h, b1h);
            }
        }
        #pragma unroll
        for (int mt = 0; mt < 2; mt++) {
            int r = mt * 16 + gr;
            int c = it * 128 + n0 + gc;
            unsigned pc0 = (unsigned)c ^ ((unsigned)(r & 7) << 2);
            unsigned pc1 = (unsigned)c ^ ((unsigned)((r + 8) & 7) << 2);
            *(float2*)&Ssc[r * 1024 + pc0] = make_float2(acc[mt][0] * 0.125f, acc[mt][1] * 0.125f);
            *(float2*)&Ssc[(r + 8) * 1024 + pc1] = make_float2(acc[mt][2] * 0.125f, acc[mt][3] * 0.125f);
        }
    }

    load_vt512(ring, Vhp, Vlp, 0, tid);
    __syncthreads();
    load_vt512(ring + ABUF, Vhp, Vlp, 1, tid);

    // ---- register-resident masked softmax (bitmask) + fused S->P ----
    #pragma unroll 1
    for (int rr = 0; rr < 2; rr++) {
        int r = wid * 2 + rr;
        int qg = q0 + r;
        unsigned xr = (unsigned)(r & 7) << 2;
        const unsigned* mb = g_mbits + (size_t)(b * 1024 + qg) * 32;
        float* srow = &Ssc[r * 1024];

        unsigned wv[16];
        #pragma unroll
        for (int i = 0; i < 16; i++) wv[i] = __ldg(&mb[(lane >> 4) + 2 * i]);

        unsigned wl = __ldg(&mb[lane]);
        int pc = __popc(wl);
        #pragma unroll
        for (int o = 16; o; o >>= 1) pc += __shfl_xor_sync(0xffffffffu, pc, o);
        unsigned wdiag = __shfl_sync(0xffffffffu, wl, qg >> 5);
        int cnt = pc + (((wdiag >> (qg & 31)) & 1u) ? 0 : 1);

        float treg[32];
        float mx = 0.f;
        unsigned bp = ((unsigned)lane * 2) & 31;
        #pragma unroll
        for (int i = 0; i < 16; i++) {
            int kk = lane * 2 + 64 * i;
            float2 s = *(float2*)&srow[(unsigned)kk ^ xr];
            bool a0 = (kk != qg) && !((wv[i] >> bp) & 1u);
            bool a1 = (kk + 1 != qg) && !((wv[i] >> (bp + 1)) & 1u);
            float t0 = a0 ? s.x : 0.f;
            float t1 = a1 ? s.y : 0.f;
            treg[2 * i] = t0; treg[2 * i + 1] = t1;
            mx = fmaxf(mx, fmaxf(t0, t1));
        }
        #pragma unroll
        for (int o = 16; o; o >>= 1)
            mx = fmaxf(mx, __shfl_xor_sync(0xffffffffu, mx, o));
        float sum = 0.f;
        #pragma unroll
        for (int j = 0; j < 32; j++) {
            float e = (treg[j] != 0.f) ? __expf(treg[j] - mx) : 0.f;
            treg[j] = e;
            sum += e;
        }
        #pragma unroll
        for (int o = 16; o; o >>= 1) sum += __shfl_xor_sync(0xffffffffu, sum, o);
        float Z = sum + (float)cnt * __expf(-mx);
        float inv = 1.f / (sum + 1e-13f * Z);
        float* orow = attn_out + (((size_t)h * NB + b) * 1024 + qg) * 1024;
        #pragma unroll
        for (int i = 0; i < 16; i++) {
            int kk = lane * 2 + 64 * i;
            float a0 = treg[2 * i] * inv, a1 = treg[2 * i + 1] * inv;
            *(float2*)&orow[kk] = make_float2(a0, a1);
            unsigned slot = (unsigned)((kk >> 3) ^ (r & 7));
            unsigned word = ((unsigned)kk >> 1) & 3;
            *(unsigned*)(smc + (size_t)r * 4096 + (slot << 4) + word * 4) = pack_hi(a0, a1);
            *(unsigned*)(smc + (size_t)r * 4096 + (slot << 4) + word * 4 + 2048) = pack_lo(a0, a1);
        }
    }
    __syncthreads();

    // ---- pass 2: out = P V (wk4 x wn4) ----
    float pacc[2][2][4];
    #pragma unroll
    for (int a = 0; a < 2; a++)
        #pragma unroll
        for (int c = 0; c < 2; c++)
            #pragma unroll
            for (int e = 0; e < 4; e++) pacc[a][c][e] = 0.f;
    int wk = wid >> 2, wn = wid & 3;

    #pragma unroll 1
    for (int kt = 0; kt < 8; kt++) {
        asm volatile("cp.async.wait_group 1;" ::: "memory");
        __syncthreads();
        if (kt + 2 < 8) load_vt512(ring + (unsigned)((kt + 2) % 3) * ABUF, Vhp, Vlp, kt + 2, tid);
        else asm volatile("cp.async.commit_group;");

        unsigned buf = ring + (unsigned)(kt % 3) * ABUF;
        #pragma unroll
        for (int i = 0; i < 2; i++) {
            int s8 = wk * 2 + i;
            int kseg = kt * 8 + s8;
            unsigned pf[2][2][4];
            #pragma unroll
            for (int v = 0; v < 2; v++)
                #pragma unroll
                for (int mt = 0; mt < 2; mt++) {
                    int r = mt * 16 + rA;
                    unsigned slot = (unsigned)((v * 128 + kseg * 2 + chv) ^ (r & 7));
                    ldm4(pf[v][mt][0], pf[v][mt][1], pf[v][mt][2], pf[v][mt][3],
                         sb + r * 4096 + (slot << 4));
                }
            unsigned bh4[4], bl4[4];
            int krow = s8 * 16 + rA;
            unsigned ob = krow * 128 + ((unsigned)((wn * 2 + chv) ^ (krow & 7)) << 4);
            ldm4t(bh4[0], bh4[1], bh4[2], bh4[3], buf + ob);
            ldm4t(bl4[0], bl4[1], bl4[2], bl4[3], buf + 16384 + ob);
            #pragma unroll
            for (int mt = 0; mt < 2; mt++)
                #pragma unroll
                for (int nt = 0; nt < 2; nt++) {
                    mma_bf16(pacc[mt][nt], pf[0][mt], bh4[nt * 2], bh4[nt * 2 + 1]);
                    mma_bf16(pacc[mt][nt], pf[0][mt], bl4[nt * 2], bl4[nt * 2 + 1]);
                    mma_bf16(pacc[mt][nt], pf[1][mt], bh4[nt * 2], bh4[nt * 2 + 1]);
                }
        }
    }
    asm volatile("cp.async.wait_group 0;" ::: "memory");
    __syncthreads();

    float* red = (float*)(smc + AKB);
    if (wk > 0) {
        int base = (wk - 1) * 2048;
        #pragma unroll
        for (int mt = 0; mt < 2; mt++)
            #pragma unroll
            for (int nt = 0; nt < 2; nt++) {
                int rr0 = mt * 16 + gr;
                int cc0 = wn * 16 + nt * 8 + gc;
                red[base + rr0 * 64 + cc0]     = pacc[mt][nt][0];
                red[base + rr0 * 64 + cc0 + 1] = pacc[mt][nt][1];
                red[base + (rr0 + 8) * 64 + cc0]     = pacc[mt][nt][2];
                red[base + (rr0 + 8) * 64 + cc0 + 1] = pacc[mt][nt][3];
            }
    }
    __syncthreads();
    if (wk == 0) {
        #pragma unroll
        for (int mt = 0; mt < 2; mt++)
            #pragma unroll
            for (int nt = 0; nt < 2; nt++) {
                int rr0 = mt * 16 + gr;
                int cc0 = wn * 16 + nt * 8 + gc;
                float v0 = pacc[mt][nt][0], v1 = pacc[mt][nt][1];
                float v2 = pacc[mt][nt][2], v3 = pacc[mt][nt][3];
                #pragma unroll
                for (int g = 0; g < 3; g++) {
                    v0 += red[g * 2048 + rr0 * 64 + cc0];
                    v1 += red[g * 2048 + rr0 * 64 + cc0 + 1];
                    v2 += red[g * 2048 + (rr0 + 8) * 64 + cc0];
                    v3 += red[g * 2048 + (rr0 + 8) * 64 + cc0 + 1];
                }
                size_t p0 = ((size_t)b * 1024 + q0 + rr0) * 512 + h * 64 + cc0;
                size_t p1 = p0 + 8 * 512;
                store_hl2(&g_atth[p0], &g_attl[p0], v0, v1);
                store_hl2(&g_atth[p1], &g_attl[p1], v2, v3);
            }
    }
}

// ---------------- launch ----------------
extern "C" void kernel_launch(void* const* d_in, const int* in_sizes, int n_in,
                              void* d_out, int out_size)
{
    (void)in_sizes; (void)n_in; (void)out_size;
    const float* q   = (const float*)d_in[0];
    const float* k   = (const float*)d_in[1];
    const float* v   = (const float*)d_in[2];
    const int*   msk = (const int*)d_in[3];
    const float* Wq  = (const float*)d_in[4];
    const float* Wk  = (const float*)d_in[5];
    const float* Wv  = (const float*)d_in[6];
    const float* Wfc = (const float*)d_in[7];
    const float* g1  = (const float*)d_in[8];
    const float* b1  = (const float*)d_in[9];
    const float* g2  = (const float*)d_in[10];
    const float* b2  = (const float*)d_in[11];
    const float* g3  = (const float*)d_in[12];
    const float* b3  = (const float*)d_in[13];

    float* out = (float*)d_out;
    float* dyn_out  = out;                            // [16,1024,512]
    float* attn_out = out + (size_t)MROWS * 512;      // [128,1024,1024]

    const int gemm_smem = 4 * STG;                    // 98304 B -> 2 CTAs/SM
    const int attn_smem = 131072 + 3 * 32768;         // 229376 B
    cudaFuncSetAttribute(gemm_mma_kernel, cudaFuncAttributeMaxDynamicSharedMemorySize, gemm_smem);
    cudaFuncSetAttribute(attn_mma_kernel, cudaFuncAttributeMaxDynamicSharedMemorySize, attn_smem);

    pack_mask_kernel<<<2048, 256>>>(msk);
    ln_fused_kernel<<<dim3(2048, 3), 256>>>(q, k, v, g1, b1, g2, b2, g3, b3);
    convert_w_kernel<<<1024, 256>>>(Wq, Wk, Wv, Wfc);
    gemm_mma_kernel<<<dim3(8, 128, 3), 256, gemm_smem>>>(nullptr, 0);   // Q,K,V projections
    attn_mma_kernel<<<dim3(32, 128), 512, attn_smem>>>(msk, attn_out);
    gemm_mma_kernel<<<dim3(8, 128, 1), 256, gemm_smem>>>(dyn_out, 1);   // fc
}

// round 15
// speedup vs baseline: 1.5507x; 1.0105x over previous
#include <cuda_runtime.h>
#include <cuda_bf16.h>

#define NB 16
#define NL 1024
#define NH 8
#define MROWS (NB*NL)

// ---------------- scratch ----------------
__device__ __align__(16) __nv_bfloat16 g_Qh[NB*NH*NL*64];
__device__ __align__(16) __nv_bfloat16 g_Ql[NB*NH*NL*64];
__device__ __align__(16) __nv_bfloat16 g_Kh[NB*NH*NL*64];
__device__ __align__(16) __nv_bfloat16 g_Kl[NB*NH*NL*64];
__device__ __align__(16) __nv_bfloat16 g_Vh[NB*NH*NL*64];
__device__ __align__(16) __nv_bfloat16 g_Vl[NB*NH*NL*64];
__device__ __align__(16) __nv_bfloat16 g_Ah[3][MROWS*512];
__device__ __align__(16) __nv_bfloat16 g_Al[3][MROWS*512];
__device__ __align__(16) __nv_bfloat16 g_Wh[4][512*512];
__device__ __align__(16) __nv_bfloat16 g_Wl[4][512*512];
__device__ __align__(16) __nv_bfloat16 g_atth[MROWS*512];
__device__ __align__(16) __nv_bfloat16 g_attl[MROWS*512];
__device__ __align__(16) unsigned g_mbits[NB*NL*32];   // 2MB packed mask bits

// ---------------- helpers ----------------
__device__ __forceinline__ unsigned smem_u32(const void* p) {
    unsigned a;
    asm("{ .reg .u64 t; cvta.to.shared.u64 t, %1; cvt.u32.u64 %0, t; }" : "=r"(a) : "l"(p));
    return a;
}
__device__ __forceinline__ void cp16(unsigned dst, const void* src) {
    asm volatile("cp.async.cg.shared.global [%0], [%1], 16;" :: "r"(dst), "l"(src));
}
__device__ __forceinline__ void ldm4(unsigned& r0, unsigned& r1, unsigned& r2, unsigned& r3, unsigned a) {
    asm volatile("ldmatrix.sync.aligned.m8n8.x4.shared.b16 {%0,%1,%2,%3}, [%4];"
                 : "=r"(r0), "=r"(r1), "=r"(r2), "=r"(r3) : "r"(a));
}
__device__ __forceinline__ void ldm2(unsigned& r0, unsigned& r1, unsigned a) {
    asm volatile("ldmatrix.sync.aligned.m8n8.x2.shared.b16 {%0,%1}, [%2];"
                 : "=r"(r0), "=r"(r1) : "r"(a));
}
__device__ __forceinline__ void ldm4t(unsigned& r0, unsigned& r1, unsigned& r2, unsigned& r3, unsigned a) {
    asm volatile("ldmatrix.sync.aligned.m8n8.x4.trans.shared.b16 {%0,%1,%2,%3}, [%4];"
                 : "=r"(r0), "=r"(r1), "=r"(r2), "=r"(r3) : "r"(a));
}
__device__ __forceinline__ void mma_bf16(float* d, const unsigned* a, unsigned b0, unsigned b1) {
    asm volatile(
        "mma.sync.aligned.m16n8k16.row.col.f32.bf16.bf16.f32 "
        "{%0,%1,%2,%3}, {%4,%5,%6,%7}, {%8,%9}, {%0,%1,%2,%3};"
        : "+f"(d[0]), "+f"(d[1]), "+f"(d[2]), "+f"(d[3])
        : "r"(a[0]), "r"(a[1]), "r"(a[2]), "r"(a[3]), "r"(b0), "r"(b1));
}
__device__ __forceinline__ void split_hl(float y, __nv_bfloat16& h, __nv_bfloat16& l) {
    h = __float2bfloat16(y);
    l = __float2bfloat16(y - __bfloat162float(h));
}
__device__ __forceinline__ void store_hl2(__nv_bfloat16* ph, __nv_bfloat16* pl, float a, float b) {
    __nv_bfloat162 H, L;
    split_hl(a, H.x, L.x);
    split_hl(b, H.y, L.y);
    *(__nv_bfloat162*)ph = H;
    *(__nv_bfloat162*)pl = L;
}
__device__ __forceinline__ unsigned pack_hi(float a, float b) {
    __nv_bfloat162 H; H.x = __float2bfloat16(a); H.y = __float2bfloat16(b);
    return *(unsigned*)&H;
}
__device__ __forceinline__ unsigned pack_lo(float a, float b) {
    __nv_bfloat16 ha = __float2bfloat16(a), hb = __float2bfloat16(b);
    __nv_bfloat162 L;
    L.x = __float2bfloat16(a - __bfloat162float(ha));
    L.y = __float2bfloat16(b - __bfloat162float(hb));
    return *(unsigned*)&L;
}

// ---------------- merged prep: pack_mask | LN+split | W split (one launch) ----------------
// blocks [0,2048): pack_mask ; [2048,8192): LN t=0..2 ; [8192,9216): convert_w
__global__ __launch_bounds__(256) void prep_kernel(
    const int* __restrict__ mask,
    const float* __restrict__ q, const float* __restrict__ k, const float* __restrict__ v,
    const float* __restrict__ g1, const float* __restrict__ b1,
    const float* __restrict__ g2, const float* __restrict__ b2,
    const float* __restrict__ g3, const float* __restrict__ b3,
    const float* __restrict__ Wq, const float* __restrict__ Wk,
    const float* __restrict__ Wv, const float* __restrict__ Wfc)
{
    int bx = blockIdx.x;
    int warp = threadIdx.x >> 5, lane = threadIdx.x & 31;

    if (bx < 2048) {
        // ---- pack mask bits ----
        int row = bx * 8 + warp;
        const int* mrow = mask + (size_t)row * 1024;
        #pragma unroll
        for (int j = 0; j < 32; j++) {
            int mv = mrow[j * 32 + lane];
            unsigned w = __ballot_sync(0xffffffffu, mv != 0);
            if (lane == 0) g_mbits[row * 32 + j] = w;
        }
        return;
    }
    if (bx < 8192) {
        // ---- LN stats + apply + hi/lo split ----
        int idx = bx - 2048;
        int t = idx >> 11;                 // 0..2
        int row = (idx & 2047) * 8 + warp;
        const float* x  = (t == 0 ? q  : (t == 1 ? k  : v))  + (size_t)row * 512;
        const float* G  = (t == 0 ? g1 : (t == 1 ? g2 : g3));
        const float* Bt = (t == 0 ? b1 : (t == 1 ? b2 : b3));

        float4 xv[4];
        float s = 0.f, ss = 0.f;
        #pragma unroll
        for (int i = 0; i < 4; i++) {
            xv[i] = ((const float4*)x)[lane + 32 * i];
            s  += xv[i].x + xv[i].y + xv[i].z + xv[i].w;
            ss += xv[i].x*xv[i].x + xv[i].y*xv[i].y + xv[i].z*xv[i].z + xv[i].w*xv[i].w;
        }
        #pragma unroll
        for (int o = 16; o; o >>= 1) {
            s  += __shfl_xor_sync(0xffffffffu, s, o);
            ss += __shfl_xor_sync(0xffffffffu, ss, o);
        }
        float mu = s * (1.f / 512.f);
        float var = ss * (1.f / 512.f) - mu * mu;
        float rs = rsqrtf(var + 1e-5f);

        __nv_bfloat16* ph = g_Ah[t] + (size_t)row * 512;
        __nv_bfloat16* pl = g_Al[t] + (size_t)row * 512;
        #pragma unroll
        for (int i = 0; i < 4; i++) {
            int c4 = lane + 32 * i;
            float4 gv = ((const float4*)G)[c4];
            float4 bv = ((const float4*)Bt)[c4];
            float y[4];
            y[0] = (xv[i].x - mu) * rs * gv.x + bv.x;
            y[1] = (xv[i].y - mu) * rs * gv.y + bv.y;
            y[2] = (xv[i].z - mu) * rs * gv.z + bv.z;
            y[3] = (xv[i].w - mu) * rs * gv.w + bv.w;
            __nv_bfloat16 hh[4], ll[4];
            #pragma unroll
            for (int j = 0; j < 4; j++) split_hl(y[j], hh[j], ll[j]);
            *(uint2*)(ph + c4 * 4) = *(uint2*)hh;
            *(uint2*)(pl + c4 * 4) = *(uint2*)ll;
        }
        return;
    }
    // ---- W hi/lo split ----
    {
        int idx = ((bx - 8192) * 256 + threadIdx.x) * 4;
        int mat = idx >> 18;
        int off = idx & 262143;
        const float* W = (mat == 0) ? Wq : ((mat == 1) ? Wk : ((mat == 2) ? Wv : Wfc));
        float4 xv = *(const float4*)(W + off);
        float y[4] = {xv.x, xv.y, xv.z, xv.w};
        __nv_bfloat16 hh[4], ll[4];
        #pragma unroll
        for (int j = 0; j < 4; j++) split_hl(y[j], hh[j], ll[j]);
        *(uint2*)(g_Wh[mat] + off) = *(uint2*)hh;
        *(uint2*)(g_Wl[mat] + off) = *(uint2*)ll;
    }
}

// ---------------- mma.sync GEMM: 256 thr, 2 CTA/SM, BM=128 BN=64 BK=32 (R13, validated) ----------------
#define STG 24576
#define VOFF_AL 8192
#define VOFF_BH 16384
#define VOFF_BL 20480

__device__ __forceinline__ void load_stage_mma(
    const __nv_bfloat16* __restrict__ Ah, const __nv_bfloat16* __restrict__ Al,
    const __nv_bfloat16* __restrict__ Bh, const __nv_bfloat16* __restrict__ Bl,
    int mr0, int nr0, int kb, unsigned dstb, int tid)
{
    {
        int m = tid >> 1, c = tid & 1;
        unsigned sw = (unsigned)(c ^ ((m >> 2) & 1)) << 4;
        #pragma unroll
        for (int kc = 0; kc < 2; kc++) {
            unsigned dst = dstb + kc * 4096 + m * 32 + sw;
            size_t ga = (size_t)(mr0 + m) * 512 + kb + kc * 16 + c * 8;
            cp16(dst,           Ah + ga);
            cp16(dst + VOFF_AL, Al + ga);
        }
    }
    {
        int m = tid >> 2, kc = (tid >> 1) & 1, c = tid & 1;
        unsigned sw = (unsigned)(c ^ ((m >> 2) & 1)) << 4;
        unsigned dst = dstb + VOFF_BH + kc * 2048 + m * 32 + sw;
        size_t gb = (size_t)(nr0 + m) * 512 + kb + kc * 16 + c * 8;
        cp16(dst,                       Bh + gb);
        cp16(dst + (VOFF_BL - VOFF_BH), Bl + gb);
    }
    asm volatile("cp.async.commit_group;");
}

__global__ __launch_bounds__(256, 2) void gemm_mma_kernel(float* __restrict__ c_fc, int mode)
{
    extern __shared__ char smem[];
    unsigned sb = smem_u32(smem);
    int tid = threadIdx.x, wid = tid >> 5, lane = tid & 31;
    int z = blockIdx.z;
    int mr0 = blockIdx.y * 128;
    int nr0 = blockIdx.x * 64;

    const __nv_bfloat16 *Ah, *Al, *Wh, *Wl;
    __nv_bfloat16 *oh = 0, *ol = 0;
    if (mode == 0) {
        Ah = g_Ah[z]; Al = g_Al[z]; Wh = g_Wh[z]; Wl = g_Wl[z];
        oh = (z == 0) ? g_Qh : ((z == 1) ? g_Kh : g_Vh);
        ol = (z == 0) ? g_Ql : ((z == 1) ? g_Kl : g_Vl);
    } else {
        Ah = g_atth; Al = g_attl; Wh = g_Wh[3]; Wl = g_Wl[3];
    }

    int rA = lane & 15, chv = lane >> 4;
    unsigned offT = (unsigned)(rA * 32 + ((chv ^ ((rA >> 2) & 1)) << 4));
    int wm = wid >> 1, wn = wid & 1;

    float acc[2][4][4];
    #pragma unroll
    for (int a = 0; a < 2; a++)
        #pragma unroll
        for (int b = 0; b < 4; b++)
            #pragma unroll
            for (int c = 0; c < 4; c++) acc[a][b][c] = 0.f;

    load_stage_mma(Ah, Al, Wh, Wl, mr0, nr0, 0,  sb,           tid);
    load_stage_mma(Ah, Al, Wh, Wl, mr0, nr0, 32, sb + STG,     tid);
    load_stage_mma(Ah, Al, Wh, Wl, mr0, nr0, 64, sb + 2 * STG, tid);

    #pragma unroll 1
    for (int s = 0; s < 16; s++) {
        if (s < 14) { asm volatile("cp.async.wait_group 2;"); }
        else        { asm volatile("cp.async.wait_group 0;"); }
        __syncthreads();
        if (s + 3 < 16)
            load_stage_mma(Ah, Al, Wh, Wl, mr0, nr0, (s + 3) * 32, sb + (unsigned)((s + 3) & 3) * STG, tid);
        unsigned buf = sb + (unsigned)(s & 3) * STG;

        #pragma unroll
        for (int kc = 0; kc < 2; kc++) {
            unsigned abase  = buf + kc * 4096;
            unsigned bbaseh = buf + VOFF_BH + kc * 2048;
            unsigned bbasel = buf + VOFF_BL + kc * 2048;
            unsigned aH[2][4], bH[2][4];
            #pragma unroll
            for (int mt = 0; mt < 2; mt++)
                ldm4(aH[mt][0], aH[mt][1], aH[mt][2], aH[mt][3],
                     abase + (unsigned)((wm * 32 + mt * 16) * 32) + offT);
            #pragma unroll
            for (int bt = 0; bt < 2; bt++)
                ldm4(bH[bt][0], bH[bt][1], bH[bt][2], bH[bt][3],
                     bbaseh + (unsigned)((wn * 32 + bt * 16) * 32) + offT);
            #pragma unroll
            for (int mt = 0; mt < 2; mt++)
                #pragma unroll
                for (int nt = 0; nt < 4; nt++)
                    mma_bf16(acc[mt][nt], aH[mt], bH[nt >> 1][nt & 1], bH[nt >> 1][(nt & 1) + 2]);
            {
                unsigned bL[2][4];
                #pragma unroll
                for (int bt = 0; bt < 2; bt++)
                    ldm4(bL[bt][0], bL[bt][1], bL[bt][2], bL[bt][3],
                         bbasel + (unsigned)((wn * 32 + bt * 16) * 32) + offT);
                #pragma unroll
                for (int mt = 0; mt < 2; mt++)
                    #pragma unroll
                    for (int nt = 0; nt < 4; nt++)
                        mma_bf16(acc[mt][nt], aH[mt], bL[nt >> 1][nt & 1], bL[nt >> 1][(nt & 1) + 2]);
            }
            {
                unsigned aL[2][4];
                #pragma unroll
                for (int mt = 0; mt < 2; mt++)
                    ldm4(aL[mt][0], aL[mt][1], aL[mt][2], aL[mt][3],
                         abase + VOFF_AL + (unsigned)((wm * 32 + mt * 16) * 32) + offT);
                #pragma unroll
                for (int mt = 0; mt < 2; mt++)
                    #pragma unroll
                    for (int nt = 0; nt < 4; nt++)
                        mma_bf16(acc[mt][nt], aL[mt], bH[nt >> 1][nt & 1], bH[nt >> 1][(nt & 1) + 2]);
            }
        }
    }

    int gr = lane >> 2, gc = (lane & 3) * 2;
    #pragma unroll
    for (int mt = 0; mt < 2; mt++) {
        #pragma unroll
        for (int nt = 0; nt < 4; nt++) {
            int r0 = mr0 + wm * 32 + mt * 16 + gr;
            int n0 = nr0 + wn * 32 + nt * 8 + gc;
            if (mode == 0) {
                int h = n0 >> 6, d = n0 & 63;
                int r1 = r0 + 8;
                size_t p0 = ((size_t)((r0 >> 10) * 8 + h) << 16) + (size_t)(r0 & 1023) * 64 + d;
                size_t p1 = ((size_t)((r1 >> 10) * 8 + h) << 16) + (size_t)(r1 & 1023) * 64 + d;
                store_hl2(oh + p0, ol + p0, acc[mt][nt][0], acc[mt][nt][1]);
                store_hl2(oh + p1, ol + p1, acc[mt][nt][2], acc[mt][nt][3]);
            } else {
                float* p0 = c_fc + (size_t)r0 * 512 + n0;
                *(float2*)p0 = make_float2(acc[mt][nt][0], acc[mt][nt][1]);
                *(float2*)(p0 + 8 * 512) = make_float2(acc[mt][nt][2], acc[mt][nt][3]);
            }
        }
    }
}

// ---------------- tensor-core fused attention (verbatim R13 - validated 1045us) ----------------
#define AKB 131072u
#define ABUF 32768u

__device__ __forceinline__ void load_kt512(unsigned buf, const __nv_bfloat16* Kh,
                                           const __nv_bfloat16* Kl, int it, int tid)
{
    #pragma unroll
    for (int i = 0; i < 4; i++) {
        int idx = i * 512 + tid;
        int ver = idx >> 10, g = idx & 1023;
        int row = g >> 3, cc = g & 7;
        int kc = cc >> 1, ch = cc & 1;
        unsigned dst = buf + ver * 16384 + kc * 4096 + row * 32
                     + ((unsigned)(ch ^ ((row >> 2) & 1)) << 4);
        cp16(dst, (ver ? Kl : Kh) + (size_t)(it * 128 + row) * 64 + cc * 8);
    }
    asm volatile("cp.async.commit_group;");
}
__device__ __forceinline__ void load_vt512(unsigned buf, const __nv_bfloat16* Vh,
                                           const __nv_bfloat16* Vl, int it, int tid)
{
    #pragma unroll
    for (int i = 0; i < 4; i++) {
        int idx = i * 512 + tid;
        int ver = idx >> 10, g = idx & 1023;
        int row = g >> 3, cc = g & 7;
        unsigned dst = buf + ver * 16384 + row * 128 + ((unsigned)(cc ^ (row & 7)) << 4);
        cp16(dst, (ver ? Vl : Vh) + (size_t)(it * 128 + row) * 64 + cc * 8);
    }
    asm volatile("cp.async.commit_group;");
}

__global__ __launch_bounds__(512, 1) void attn_mma_kernel(
    const int* __restrict__ mask, float* __restrict__ attn_out)
{
    (void)mask;
    extern __shared__ char smc[];
    unsigned sb = smem_u32(smc);
    float* Ssc = (float*)smc;
    int tid = threadIdx.x, wid = tid >> 5, lane = tid & 31;
    int rA = lane & 15, chv = lane >> 4;
    int gr = lane >> 2, gc = (lane & 3) * 2;
    int q0 = blockIdx.x * 32;
    int bh = blockIdx.y;
    int b = bh >> 3, h = bh & 7;
    const __nv_bfloat16* Qhp = g_Qh + ((size_t)bh << 16) + (size_t)q0 * 64;
    const __nv_bfloat16* Qlp = g_Ql + ((size_t)bh << 16) + (size_t)q0 * 64;
    const __nv_bfloat16* Khp = g_Kh + ((size_t)bh << 16);
    const __nv_bfloat16* Klp = g_Kl + ((size_t)bh << 16);
    const __nv_bfloat16* Vhp = g_Vh + ((size_t)bh << 16);
    const __nv_bfloat16* Vlp = g_Vl + ((size_t)bh << 16);
    unsigned ring = sb + AKB;
    unsigned qarea = ring + 2 * ABUF;

    {
        int ver = tid >> 8, rest = tid & 255;
        int row = rest >> 3, cc = rest & 7;
        int kc = cc >> 1, ch = cc & 1;
        unsigned dst = qarea + ver * 4096 + kc * 1024 + row * 32
                     + ((unsigned)(ch ^ ((row >> 2) & 1)) << 4);
        cp16(dst, (ver ? Qlp : Qhp) + row * 64 + cc * 8);
    }
    load_kt512(ring, Khp, Klp, 0, tid);
    load_kt512(ring + ABUF, Khp, Klp, 1, tid);

    unsigned qf[2][4][2][4];
    int n0 = wid * 8;
    unsigned offAq[2];
    #pragma unroll
    for (int mt = 0; mt < 2; mt++) {
        int r = mt * 16 + rA;
        offAq[mt] = r * 32 + ((unsigned)(chv ^ ((r >> 2) & 1)) << 4);
    }
    int rB = n0 + (lane & 7);
    int chB = (lane >> 3) & 1;
    unsigned offB = rB * 32 + ((unsigned)(chB ^ ((rB >> 2) & 1)) << 4);

    #pragma unroll 1
    for (int it = 0; it < 8; it++) {
        asm volatile("cp.async.wait_group 1;" ::: "memory");
        __syncthreads();
        if (it == 0) {
            #pragma unroll
            for (int v = 0; v < 2; v++)
                #pragma unroll
                for (int kc = 0; kc < 4; kc++)
                    #pragma unroll
                    for (int mt = 0; mt < 2; mt++)
                        ldm4(qf[v][kc][mt][0], qf[v][kc][mt][1], qf[v][kc][mt][2], qf[v][kc][mt][3],
                             qarea + v * 4096 + kc * 1024 + offAq[mt]);
            __syncthreads();
        }
        if (it + 2 < 8) load_kt512(ring + (unsigned)((it + 2) % 3) * ABUF, Khp, Klp, it + 2, tid);
        else asm volatile("cp.async.commit_group;");

        unsigned buf = ring + (unsigned)(it % 3) * ABUF;
        float acc[2][4];
        #pragma unroll
        for (int a = 0; a < 2; a++)
            #pragma unroll
            for (int e = 0; e < 4; e++) acc[a][e] = 0.f;
        #pragma unroll
        for (int kc = 0; kc < 4; kc++) {
            unsigned b0h, b1h, b0l, b1l;
            ldm2(b0h, b1h, buf + kc * 4096 + offB);
            ldm2(b0l, b1l, buf + 16384 + kc * 4096 + offB);
            #pragma unroll
            for (int mt = 0; mt < 2; mt++) {
                mma_bf16(acc[mt], qf[0][kc][mt], b0h, b1h);
                mma_bf16(acc[mt], qf[0][kc][mt], b0l, b1l);
                mma_bf16(acc[mt], qf[1][kc][mt], b0h, b1h);
            }
        }
        #pragma unroll
        for (int mt = 0; mt < 2; mt++) {
            int r = mt * 16 + gr;
            int c = it * 128 + n0 + gc;
            unsigned pc0 = (unsigned)c ^ ((unsigned)(r & 7) << 2);
            unsigned pc1 = (unsigned)c ^ ((unsigned)((r + 8) & 7) << 2);
            *(float2*)&Ssc[r * 1024 + pc0] = make_float2(acc[mt][0] * 0.125f, acc[mt][1] * 0.125f);
            *(float2*)&Ssc[(r + 8) * 1024 + pc1] = make_float2(acc[mt][2] * 0.125f, acc[mt][3] * 0.125f);
        }
    }

    load_vt512(ring, Vhp, Vlp, 0, tid);
    __syncthreads();
    load_vt512(ring + ABUF, Vhp, Vlp, 1, tid);

    #pragma unroll 1
    for (int rr = 0; rr < 2; rr++) {
        int r = wid * 2 + rr;
        int qg = q0 + r;
        unsigned xr = (unsigned)(r & 7) << 2;
        const unsigned* mb = g_mbits + (size_t)(b * 1024 + qg) * 32;
        float* srow = &Ssc[r * 1024];

        unsigned wv[16];
        #pragma unroll
        for (int i = 0; i < 16; i++) wv[i] = __ldg(&mb[(lane >> 4) + 2 * i]);

        unsigned wl = __ldg(&mb[lane]);
        int pc = __popc(wl);
        #pragma unroll
        for (int o = 16; o; o >>= 1) pc += __shfl_xor_sync(0xffffffffu, pc, o);
        unsigned wdiag = __shfl_sync(0xffffffffu, wl, qg >> 5);
        int cnt = pc + (((wdiag >> (qg & 31)) & 1u) ? 0 : 1);

        float treg[32];
        float mx = 0.f;
        unsigned bp = ((unsigned)lane * 2) & 31;
        #pragma unroll
        for (int i = 0; i < 16; i++) {
            int kk = lane * 2 + 64 * i;
            float2 s = *(float2*)&srow[(unsigned)kk ^ xr];
            bool a0 = (kk != qg) && !((wv[i] >> bp) & 1u);
            bool a1 = (kk + 1 != qg) && !((wv[i] >> (bp + 1)) & 1u);
            float t0 = a0 ? s.x : 0.f;
            float t1 = a1 ? s.y : 0.f;
            treg[2 * i] = t0; treg[2 * i + 1] = t1;
            mx = fmaxf(mx, fmaxf(t0, t1));
        }
        #pragma unroll
        for (int o = 16; o; o >>= 1)
            mx = fmaxf(mx, __shfl_xor_sync(0xffffffffu, mx, o));
        float sum = 0.f;
        #pragma unroll
        for (int j = 0; j < 32; j++) {
            float e = (treg[j] != 0.f) ? __expf(treg[j] - mx) : 0.f;
            treg[j] = e;
            sum += e;
        }
        #pragma unroll
        for (int o = 16; o; o >>= 1) sum += __shfl_xor_sync(0xffffffffu, sum, o);
        float Z = sum + (float)cnt * __expf(-mx);
        float inv = 1.f / (sum + 1e-13f * Z);
        float* orow = attn_out + (((size_t)h * NB + b) * 1024 + qg) * 1024;
        #pragma unroll
        for (int i = 0; i < 16; i++) {
            int kk = lane * 2 + 64 * i;
            float a0 = treg[2 * i] * inv, a1 = treg[2 * i + 1] * inv;
            *(float2*)&orow[kk] = make_float2(a0, a1);
            unsigned slot = (unsigned)((kk >> 3) ^ (r & 7));
            unsigned word = ((unsigned)kk >> 1) & 3;
            *(unsigned*)(smc + (size_t)r * 4096 + (slot << 4) + word * 4) = pack_hi(a0, a1);
            *(unsigned*)(smc + (size_t)r * 4096 + (slot << 4) + word * 4 + 2048) = pack_lo(a0, a1);
        }
    }
    __syncthreads();

    float pacc[2][2][4];
    #pragma unroll
    for (int a = 0; a < 2; a++)
        #pragma unroll
        for (int c = 0; c < 2; c++)
            #pragma unroll
            for (int e = 0; e < 4; e++) pacc[a][c][e] = 0.f;
    int wk = wid >> 2, wn = wid & 3;

    #pragma unroll 1
    for (int kt = 0; kt < 8; kt++) {
        asm volatile("cp.async.wait_group 1;" ::: "memory");
        __syncthreads();
        if (kt + 2 < 8) load_vt512(ring + (unsigned)((kt + 2) % 3) * ABUF, Vhp, Vlp, kt + 2, tid);
        else asm volatile("cp.async.commit_group;");

        unsigned buf = ring + (unsigned)(kt % 3) * ABUF;
        #pragma unroll
        for (int i = 0; i < 2; i++) {
            int s8 = wk * 2 + i;
            int kseg = kt * 8 + s8;
            unsigned pf[2][2][4];
            #pragma unroll
            for (int v = 0; v < 2; v++)
                #pragma unroll
                for (int mt = 0; mt < 2; mt++) {
                    int r = mt * 16 + rA;
                    unsigned slot = (unsigned)((v * 128 + kseg * 2 + chv) ^ (r & 7));
                    ldm4(pf[v][mt][0], pf[v][mt][1], pf[v][mt][2], pf[v][mt][3],
                         sb + r * 4096 + (slot << 4));
                }
            unsigned bh4[4], bl4[4];
            int krow = s8 * 16 + rA;
            unsigned ob = krow * 128 + ((unsigned)((wn * 2 + chv) ^ (krow & 7)) << 4);
            ldm4t(bh4[0], bh4[1], bh4[2], bh4[3], buf + ob);
            ldm4t(bl4[0], bl4[1], bl4[2], bl4[3], buf + 16384 + ob);
            #pragma unroll
            for (int mt = 0; mt < 2; mt++)
                #pragma unroll
                for (int nt = 0; nt < 2; nt++) {
                    mma_bf16(pacc[mt][nt], pf[0][mt], bh4[nt * 2], bh4[nt * 2 + 1]);
                    mma_bf16(pacc[mt][nt], pf[0][mt], bl4[nt * 2], bl4[nt * 2 + 1]);
                    mma_bf16(pacc[mt][nt], pf[1][mt], bh4[nt * 2], bh4[nt * 2 + 1]);
                }
        }
    }
    asm volatile("cp.async.wait_group 0;" ::: "memory");
    __syncthreads();

    float* red = (float*)(smc + AKB);
    if (wk > 0) {
        int base = (wk - 1) * 2048;
        #pragma unroll
        for (int mt = 0; mt < 2; mt++)
            #pragma unroll
            for (int nt = 0; nt < 2; nt++) {
                int rr0 = mt * 16 + gr;
                int cc0 = wn * 16 + nt * 8 + gc;
                red[base + rr0 * 64 + cc0]     = pacc[mt][nt][0];
                red[base + rr0 * 64 + cc0 + 1] = pacc[mt][nt][1];
                red[base + (rr0 + 8) * 64 + cc0]     = pacc[mt][nt][2];
                red[base + (rr0 + 8) * 64 + cc0 + 1] = pacc[mt][nt][3];
            }
    }
    __syncthreads();
    if (wk == 0) {
        #pragma unroll
        for (int mt = 0; mt < 2; mt++)
            #pragma unroll
            for (int nt = 0; nt < 2; nt++) {
                int rr0 = mt * 16 + gr;
                int cc0 = wn * 16 + nt * 8 + gc;
                float v0 = pacc[mt][nt][0], v1 = pacc[mt][nt][1];
                float v2 = pacc[mt][nt][2], v3 = pacc[mt][nt][3];
                #pragma unroll
                for (int g = 0; g < 3; g++) {
                    v0 += red[g * 2048 + rr0 * 64 + cc0];
                    v1 += red[g * 2048 + rr0 * 64 + cc0 + 1];
                    v2 += red[g * 2048 + (rr0 + 8) * 64 + cc0];
                    v3 += red[g * 2048 + (rr0 + 8) * 64 + cc0 + 1];
                }
                size_t p0 = ((size_t)b * 1024 + q0 + rr0) * 512 + h * 64 + cc0;
                size_t p1 = p0 + 8 * 512;
                store_hl2(&g_atth[p0], &g_attl[p0], v0, v1);
                store_hl2(&g_atth[p1], &g_attl[p1], v2, v3);
            }
    }
}

// ---------------- launch ----------------
extern "C" void kernel_launch(void* const* d_in, const int* in_sizes, int n_in,
                              void* d_out, int out_size)
{
    (void)in_sizes; (void)n_in; (void)out_size;
    const float* q   = (const float*)d_in[0];
    const float* k   = (const float*)d_in[1];
    const float* v   = (const float*)d_in[2];
    const int*   msk = (const int*)d_in[3];
    const float* Wq  = (const float*)d_in[4];
    const float* Wk  = (const float*)d_in[5];
    const float* Wv  = (const float*)d_in[6];
    const float* Wfc = (const float*)d_in[7];
    const float* g1  = (const float*)d_in[8];
    const float* b1  = (const float*)d_in[9];
    const float* g2  = (const float*)d_in[10];
    const float* b2  = (const float*)d_in[11];
    const float* g3  = (const float*)d_in[12];
    const float* b3  = (const float*)d_in[13];

    float* out = (float*)d_out;
    float* dyn_out  = out;                            // [16,1024,512]
    float* attn_out = out + (size_t)MROWS * 512;      // [128,1024,1024]

    const int gemm_smem = 4 * STG;                    // 98304 B -> 2 CTAs/SM
    const int attn_smem = 131072 + 3 * 32768;         // 229376 B
    cudaFuncSetAttribute(gemm_mma_kernel, cudaFuncAttributeMaxDynamicSharedMemorySize, gemm_smem);
    cudaFuncSetAttribute(attn_mma_kernel, cudaFuncAttributeMaxDynamicSharedMemorySize, attn_smem);

    prep_kernel<<<9216, 256>>>(msk, q, k, v, g1, b1, g2, b2, g3, b3, Wq, Wk, Wv, Wfc);
    gemm_mma_kernel<<<dim3(8, 128, 3), 256, gemm_smem>>>(nullptr, 0);   // Q,K,V projections
    attn_mma_kernel<<<dim3(32, 128), 512, attn_smem>>>(msk, attn_out);
    gemm_mma_kernel<<<dim3(8, 128, 1), 256, gemm_smem>>>(dyn_out, 1);   // fc
}

// round 16
// speedup vs baseline: 1.5807x; 1.0194x over previous
#include <cuda_runtime.h>
#include <cuda_bf16.h>

#define NB 16
#define NL 1024
#define NH 8
#define MROWS (NB*NL)

// ---------------- scratch ----------------
__device__ __align__(16) __nv_bfloat16 g_Qh[NB*NH*NL*64];
__device__ __align__(16) __nv_bfloat16 g_Ql[NB*NH*NL*64];
__device__ __align__(16) __nv_bfloat16 g_Kh[NB*NH*NL*64];
__device__ __align__(16) __nv_bfloat16 g_Kl[NB*NH*NL*64];
__device__ __align__(16) __nv_bfloat16 g_Vh[NB*NH*NL*64];
__device__ __align__(16) __nv_bfloat16 g_Vl[NB*NH*NL*64];
__device__ __align__(16) __nv_bfloat16 g_Ah[3][MROWS*512];
__device__ __align__(16) __nv_bfloat16 g_Al[3][MROWS*512];
__device__ __align__(16) __nv_bfloat16 g_Wh[4][512*512];
__device__ __align__(16) __nv_bfloat16 g_Wl[4][512*512];
__device__ __align__(16) __nv_bfloat16 g_atth[MROWS*512];
__device__ __align__(16) __nv_bfloat16 g_attl[MROWS*512];
__device__ __align__(16) unsigned g_mbits[NB*NL*32];   // 2MB packed mask bits

// ---------------- helpers ----------------
__device__ __forceinline__ unsigned smem_u32(const void* p) {
    unsigned a;
    asm("{ .reg .u64 t; cvta.to.shared.u64 t, %1; cvt.u32.u64 %0, t; }" : "=r"(a) : "l"(p));
    return a;
}
__device__ __forceinline__ void cp16(unsigned dst, const void* src) {
    asm volatile("cp.async.cg.shared.global [%0], [%1], 16;" :: "r"(dst), "l"(src));
}
__device__ __forceinline__ void ldm4(unsigned& r0, unsigned& r1, unsigned& r2, unsigned& r3, unsigned a) {
    asm volatile("ldmatrix.sync.aligned.m8n8.x4.shared.b16 {%0,%1,%2,%3}, [%4];"
                 : "=r"(r0), "=r"(r1), "=r"(r2), "=r"(r3) : "r"(a));
}
__device__ __forceinline__ void ldm2(unsigned& r0, unsigned& r1, unsigned a) {
    asm volatile("ldmatrix.sync.aligned.m8n8.x2.shared.b16 {%0,%1}, [%2];"
                 : "=r"(r0), "=r"(r1) : "r"(a));
}
__device__ __forceinline__ void ldm4t(unsigned& r0, unsigned& r1, unsigned& r2, unsigned& r3, unsigned a) {
    asm volatile("ldmatrix.sync.aligned.m8n8.x4.trans.shared.b16 {%0,%1,%2,%3}, [%4];"
                 : "=r"(r0), "=r"(r1), "=r"(r2), "=r"(r3) : "r"(a));
}
__device__ __forceinline__ void mma_bf16(float* d, const unsigned* a, unsigned b0, unsigned b1) {
    asm volatile(
        "mma.sync.aligned.m16n8k16.row.col.f32.bf16.bf16.f32 "
        "{%0,%1,%2,%3}, {%4,%5,%6,%7}, {%8,%9}, {%0,%1,%2,%3};"
        : "+f"(d[0]), "+f"(d[1]), "+f"(d[2]), "+f"(d[3])
        : "r"(a[0]), "r"(a[1]), "r"(a[2]), "r"(a[3]), "r"(b0), "r"(b1));
}
__device__ __forceinline__ void split_hl(float y, __nv_bfloat16& h, __nv_bfloat16& l) {
    h = __float2bfloat16(y);
    l = __float2bfloat16(y - __bfloat162float(h));
}
__device__ __forceinline__ void store_hl2(__nv_bfloat16* ph, __nv_bfloat16* pl, float a, float b) {
    __nv_bfloat162 H, L;
    split_hl(a, H.x, L.x);
    split_hl(b, H.y, L.y);
    *(__nv_bfloat162*)ph = H;
    *(__nv_bfloat162*)pl = L;
}
__device__ __forceinline__ unsigned pack_hi(float a, float b) {
    __nv_bfloat162 H; H.x = __float2bfloat16(a); H.y = __float2bfloat16(b);
    return *(unsigned*)&H;
}
__device__ __forceinline__ unsigned pack_lo(float a, float b) {
    __nv_bfloat16 ha = __float2bfloat16(a), hb = __float2bfloat16(b);
    __nv_bfloat162 L;
    L.x = __float2bfloat16(a - __bfloat162float(ha));
    L.y = __float2bfloat16(b - __bfloat162float(hb));
    return *(unsigned*)&L;
}

// ---------------- merged prep: pack_mask | LN+split | W split ----------------
__global__ __launch_bounds__(256) void prep_kernel(
    const int* __restrict__ mask,
    const float* __restrict__ q, const float* __restrict__ k, const float* __restrict__ v,
    const float* __restrict__ g1, const float* __restrict__ b1,
    const float* __restrict__ g2, const float* __restrict__ b2,
    const float* __restrict__ g3, const float* __restrict__ b3,
    const float* __restrict__ Wq, const float* __restrict__ Wk,
    const float* __restrict__ Wv, const float* __restrict__ Wfc)
{
    int bx = blockIdx.x;
    int warp = threadIdx.x >> 5, lane = threadIdx.x & 31;

    if (bx < 2048) {
        int row = bx * 8 + warp;
        const int* mrow = mask + (size_t)row * 1024;
        #pragma unroll
        for (int j = 0; j < 32; j++) {
            int mv = mrow[j * 32 + lane];
            unsigned w = __ballot_sync(0xffffffffu, mv != 0);
            if (lane == 0) g_mbits[row * 32 + j] = w;
        }
        return;
    }
    if (bx < 8192) {
        int idx = bx - 2048;
        int t = idx >> 11;
        int row = (idx & 2047) * 8 + warp;
        const float* x  = (t == 0 ? q  : (t == 1 ? k  : v))  + (size_t)row * 512;
        const float* G  = (t == 0 ? g1 : (t == 1 ? g2 : g3));
        const float* Bt = (t == 0 ? b1 : (t == 1 ? b2 : b3));

        float4 xv[4];
        float s = 0.f, ss = 0.f;
        #pragma unroll
        for (int i = 0; i < 4; i++) {
            xv[i] = ((const float4*)x)[lane + 32 * i];
            s  += xv[i].x + xv[i].y + xv[i].z + xv[i].w;
            ss += xv[i].x*xv[i].x + xv[i].y*xv[i].y + xv[i].z*xv[i].z + xv[i].w*xv[i].w;
        }
        #pragma unroll
        for (int o = 16; o; o >>= 1) {
            s  += __shfl_xor_sync(0xffffffffu, s, o);
            ss += __shfl_xor_sync(0xffffffffu, ss, o);
        }
        float mu = s * (1.f / 512.f);
        float var = ss * (1.f / 512.f) - mu * mu;
        float rs = rsqrtf(var + 1e-5f);

        __nv_bfloat16* ph = g_Ah[t] + (size_t)row * 512;
        __nv_bfloat16* pl = g_Al[t] + (size_t)row * 512;
        #pragma unroll
        for (int i = 0; i < 4; i++) {
            int c4 = lane + 32 * i;
            float4 gv = ((const float4*)G)[c4];
            float4 bv = ((const float4*)Bt)[c4];
            float y[4];
            y[0] = (xv[i].x - mu) * rs * gv.x + bv.x;
            y[1] = (xv[i].y - mu) * rs * gv.y + bv.y;
            y[2] = (xv[i].z - mu) * rs * gv.z + bv.z;
            y[3] = (xv[i].w - mu) * rs * gv.w + bv.w;
            __nv_bfloat16 hh[4], ll[4];
            #pragma unroll
            for (int j = 0; j < 4; j++) split_hl(y[j], hh[j], ll[j]);
            *(uint2*)(ph + c4 * 4) = *(uint2*)hh;
            *(uint2*)(pl + c4 * 4) = *(uint2*)ll;
        }
        return;
    }
    {
        int idx = ((bx - 8192) * 256 + threadIdx.x) * 4;
        int mat = idx >> 18;
        int off = idx & 262143;
        const float* W = (mat == 0) ? Wq : ((mat == 1) ? Wk : ((mat == 2) ? Wv : Wfc));
        float4 xv = *(const float4*)(W + off);
        float y[4] = {xv.x, xv.y, xv.z, xv.w};
        __nv_bfloat16 hh[4], ll[4];
        #pragma unroll
        for (int j = 0; j < 4; j++) split_hl(y[j], hh[j], ll[j]);
        *(uint2*)(g_Wh[mat] + off) = *(uint2*)hh;
        *(uint2*)(g_Wl[mat] + off) = *(uint2*)ll;
    }
}

// ---------------- mma.sync GEMM (R13/R14, validated) ----------------
#define STG 24576
#define VOFF_AL 8192
#define VOFF_BH 16384
#define VOFF_BL 20480

__device__ __forceinline__ void load_stage_mma(
    const __nv_bfloat16* __restrict__ Ah, const __nv_bfloat16* __restrict__ Al,
    const __nv_bfloat16* __restrict__ Bh, const __nv_bfloat16* __restrict__ Bl,
    int mr0, int nr0, int kb, unsigned dstb, int tid)
{
    {
        int m = tid >> 1, c = tid & 1;
        unsigned sw = (unsigned)(c ^ ((m >> 2) & 1)) << 4;
        #pragma unroll
        for (int kc = 0; kc < 2; kc++) {
            unsigned dst = dstb + kc * 4096 + m * 32 + sw;
            size_t ga = (size_t)(mr0 + m) * 512 + kb + kc * 16 + c * 8;
            cp16(dst,           Ah + ga);
            cp16(dst + VOFF_AL, Al + ga);
        }
    }
    {
        int m = tid >> 2, kc = (tid >> 1) & 1, c = tid & 1;
        unsigned sw = (unsigned)(c ^ ((m >> 2) & 1)) << 4;
        unsigned dst = dstb + VOFF_BH + kc * 2048 + m * 32 + sw;
        size_t gb = (size_t)(nr0 + m) * 512 + kb + kc * 16 + c * 8;
        cp16(dst,                       Bh + gb);
        cp16(dst + (VOFF_BL - VOFF_BH), Bl + gb);
    }
    asm volatile("cp.async.commit_group;");
}

__global__ __launch_bounds__(256, 2) void gemm_mma_kernel(float* __restrict__ c_fc, int mode)
{
    extern __shared__ char smem[];
    unsigned sb = smem_u32(smem);
    int tid = threadIdx.x, wid = tid >> 5, lane = tid & 31;
    int z = blockIdx.z;
    int mr0 = blockIdx.y * 128;
    int nr0 = blockIdx.x * 64;

    const __nv_bfloat16 *Ah, *Al, *Wh, *Wl;
    __nv_bfloat16 *oh = 0, *ol = 0;
    if (mode == 0) {
        Ah = g_Ah[z]; Al = g_Al[z]; Wh = g_Wh[z]; Wl = g_Wl[z];
        oh = (z == 0) ? g_Qh : ((z == 1) ? g_Kh : g_Vh);
        ol = (z == 0) ? g_Ql : ((z == 1) ? g_Kl : g_Vl);
    } else {
        Ah = g_atth; Al = g_attl; Wh = g_Wh[3]; Wl = g_Wl[3];
    }

    int rA = lane & 15, chv = lane >> 4;
    unsigned offT = (unsigned)(rA * 32 + ((chv ^ ((rA >> 2) & 1)) << 4));
    int wm = wid >> 1, wn = wid & 1;

    float acc[2][4][4];
    #pragma unroll
    for (int a = 0; a < 2; a++)
        #pragma unroll
        for (int b = 0; b < 4; b++)
            #pragma unroll
            for (int c = 0; c < 4; c++) acc[a][b][c] = 0.f;

    load_stage_mma(Ah, Al, Wh, Wl, mr0, nr0, 0,  sb,           tid);
    load_stage_mma(Ah, Al, Wh, Wl, mr0, nr0, 32, sb + STG,     tid);
    load_stage_mma(Ah, Al, Wh, Wl, mr0, nr0, 64, sb + 2 * STG, tid);

    #pragma unroll 1
    for (int s = 0; s < 16; s++) {
        if (s < 14) { asm volatile("cp.async.wait_group 2;"); }
        else        { asm volatile("cp.async.wait_group 0;"); }
        __syncthreads();
        if (s + 3 < 16)
            load_stage_mma(Ah, Al, Wh, Wl, mr0, nr0, (s + 3) * 32, sb + (unsigned)((s + 3) & 3) * STG, tid);
        unsigned buf = sb + (unsigned)(s & 3) * STG;

        #pragma unroll
        for (int kc = 0; kc < 2; kc++) {
            unsigned abase  = buf + kc * 4096;
            unsigned bbaseh = buf + VOFF_BH + kc * 2048;
            unsigned bbasel = buf + VOFF_BL + kc * 2048;
            unsigned aH[2][4], bH[2][4];
            #pragma unroll
            for (int mt = 0; mt < 2; mt++)
                ldm4(aH[mt][0], aH[mt][1], aH[mt][2], aH[mt][3],
                     abase + (unsigned)((wm * 32 + mt * 16) * 32) + offT);
            #pragma unroll
            for (int bt = 0; bt < 2; bt++)
                ldm4(bH[bt][0], bH[bt][1], bH[bt][2], bH[bt][3],
                     bbaseh + (unsigned)((wn * 32 + bt * 16) * 32) + offT);
            #pragma unroll
            for (int mt = 0; mt < 2; mt++)
                #pragma unroll
                for (int nt = 0; nt < 4; nt++)
                    mma_bf16(acc[mt][nt], aH[mt], bH[nt >> 1][nt & 1], bH[nt >> 1][(nt & 1) + 2]);
            {
                unsigned bL[2][4];
                #pragma unroll
                for (int bt = 0; bt < 2; bt++)
                    ldm4(bL[bt][0], bL[bt][1], bL[bt][2], bL[bt][3],
                         bbasel + (unsigned)((wn * 32 + bt * 16) * 32) + offT);
                #pragma unroll
                for (int mt = 0; mt < 2; mt++)
                    #pragma unroll
                    for (int nt = 0; nt < 4; nt++)
                        mma_bf16(acc[mt][nt], aH[mt], bL[nt >> 1][nt & 1], bL[nt >> 1][(nt & 1) + 2]);
            }
            {
                unsigned aL[2][4];
                #pragma unroll
                for (int mt = 0; mt < 2; mt++)
                    ldm4(aL[mt][0], aL[mt][1], aL[mt][2], aL[mt][3],
                         abase + VOFF_AL + (unsigned)((wm * 32 + mt * 16) * 32) + offT);
                #pragma unroll
                for (int mt = 0; mt < 2; mt++)
                    #pragma unroll
                    for (int nt = 0; nt < 4; nt++)
                        mma_bf16(acc[mt][nt], aL[mt], bH[nt >> 1][nt & 1], bH[nt >> 1][(nt & 1) + 2]);
            }
        }
    }

    int gr = lane >> 2, gc = (lane & 3) * 2;
    #pragma unroll
    for (int mt = 0; mt < 2; mt++) {
        #pragma unroll
        for (int nt = 0; nt < 4; nt++) {
            int r0 = mr0 + wm * 32 + mt * 16 + gr;
            int n0 = nr0 + wn * 32 + nt * 8 + gc;
            if (mode == 0) {
                int h = n0 >> 6, d = n0 & 63;
                int r1 = r0 + 8;
                size_t p0 = ((size_t)((r0 >> 10) * 8 + h) << 16) + (size_t)(r0 & 1023) * 64 + d;
                size_t p1 = ((size_t)((r1 >> 10) * 8 + h) << 16) + (size_t)(r1 & 1023) * 64 + d;
                store_hl2(oh + p0, ol + p0, acc[mt][nt][0], acc[mt][nt][1]);
                store_hl2(oh + p1, ol + p1, acc[mt][nt][2], acc[mt][nt][3]);
            } else {
                float* p0 = c_fc + (size_t)r0 * 512 + n0;
                *(float2*)p0 = make_float2(acc[mt][nt][0], acc[mt][nt][1]);
                *(float2*)(p0 + 8 * 512) = make_float2(acc[mt][nt][2], acc[mt][nt][3]);
            }
        }
    }
}

// ---------------- tensor-core fused attention (R14 + no-max softmax) ----------------
#define AKB 131072u
#define ABUF 32768u

__device__ __forceinline__ void load_kt512(unsigned buf, const __nv_bfloat16* Kh,
                                           const __nv_bfloat16* Kl, int it, int tid)
{
    #pragma unroll
    for (int i = 0; i < 4; i++) {
        int idx = i * 512 + tid;
        int ver = idx >> 10, g = idx & 1023;
        int row = g >> 3, cc = g & 7;
        int kc = cc >> 1, ch = cc & 1;
        unsigned dst = buf + ver * 16384 + kc * 4096 + row * 32
                     + ((unsigned)(ch ^ ((row >> 2) & 1)) << 4);
        cp16(dst, (ver ? Kl : Kh) + (size_t)(it * 128 + row) * 64 + cc * 8);
    }
    asm volatile("cp.async.commit_group;");
}
__device__ __forceinline__ void load_vt512(unsigned buf, const __nv_bfloat16* Vh,
                                           const __nv_bfloat16* Vl, int it, int tid)
{
    #pragma unroll
    for (int i = 0; i < 4; i++) {
        int idx = i * 512 + tid;
        int ver = idx >> 10, g = idx & 1023;
        int row = g >> 3, cc = g & 7;
        unsigned dst = buf + ver * 16384 + row * 128 + ((unsigned)(cc ^ (row & 7)) << 4);
        cp16(dst, (ver ? Vl : Vh) + (size_t)(it * 128 + row) * 64 + cc * 8);
    }
    asm volatile("cp.async.commit_group;");
}

__global__ __launch_bounds__(512, 1) void attn_mma_kernel(
    const int* __restrict__ mask, float* __restrict__ attn_out)
{
    (void)mask;
    extern __shared__ char smc[];
    unsigned sb = smem_u32(smc);
    float* Ssc = (float*)smc;
    int tid = threadIdx.x, wid = tid >> 5, lane = tid & 31;
    int rA = lane & 15, chv = lane >> 4;
    int gr = lane >> 2, gc = (lane & 3) * 2;
    int q0 = blockIdx.x * 32;
    int bh = blockIdx.y;
    int b = bh >> 3, h = bh & 7;
    const __nv_bfloat16* Qhp = g_Qh + ((size_t)bh << 16) + (size_t)q0 * 64;
    const __nv_bfloat16* Qlp = g_Ql + ((size_t)bh << 16) + (size_t)q0 * 64;
    const __nv_bfloat16* Khp = g_Kh + ((size_t)bh << 16);
    const __nv_bfloat16* Klp = g_Kl + ((size_t)bh << 16);
    const __nv_bfloat16* Vhp = g_Vh + ((size_t)bh << 16);
    const __nv_bfloat16* Vlp = g_Vl + ((size_t)bh << 16);
    unsigned ring = sb + AKB;
    unsigned qarea = ring + 2 * ABUF;

    {
        int ver = tid >> 8, rest = tid & 255;
        int row = rest >> 3, cc = rest & 7;
        int kc = cc >> 1, ch = cc & 1;
        unsigned dst = qarea + ver * 4096 + kc * 1024 + row * 32
                     + ((unsigned)(ch ^ ((row >> 2) & 1)) << 4);
        cp16(dst, (ver ? Qlp : Qhp) + row * 64 + cc * 8);
    }
    load_kt512(ring, Khp, Klp, 0, tid);
    load_kt512(ring + ABUF, Khp, Klp, 1, tid);

    unsigned qf[2][4][2][4];
    int n0 = wid * 8;
    unsigned offAq[2];
    #pragma unroll
    for (int mt = 0; mt < 2; mt++) {
        int r = mt * 16 + rA;
        offAq[mt] = r * 32 + ((unsigned)(chv ^ ((r >> 2) & 1)) << 4);
    }
    int rB = n0 + (lane & 7);
    int chB = (lane >> 3) & 1;
    unsigned offB = rB * 32 + ((unsigned)(chB ^ ((rB >> 2) & 1)) << 4);

    // ---- pass 1: S = Q K^T / 8 ----
    #pragma unroll 1
    for (int it = 0; it < 8; it++) {
        asm volatile("cp.async.wait_group 1;" ::: "memory");
        __syncthreads();
        if (it == 0) {
            #pragma unroll
            for (int v = 0; v < 2; v++)
                #pragma unroll
                for (int kc = 0; kc < 4; kc++)
                    #pragma unroll
                    for (int mt = 0; mt < 2; mt++)
                        ldm4(qf[v][kc][mt][0], qf[v][kc][mt][1], qf[v][kc][mt][2], qf[v][kc][mt][3],
                             qarea + v * 4096 + kc * 1024 + offAq[mt]);
            __syncthreads();
        }
        if (it + 2 < 8) load_kt512(ring + (unsigned)((it + 2) % 3) * ABUF, Khp, Klp, it + 2, tid);
        else asm volatile("cp.async.commit_group;");

        unsigned buf = ring + (unsigned)(it % 3) * ABUF;
        float acc[2][4];
        #pragma unroll
        for (int a = 0; a < 2; a++)
            #pragma unroll
            for (int e = 0; e < 4; e++) acc[a][e] = 0.f;
        #pragma unroll
        for (int kc = 0; kc < 4; kc++) {
            unsigned b0h, b1h, b0l, b1l;
            ldm2(b0h, b1h, buf + kc * 4096 + offB);
            ldm2(b0l, b1l, buf + 16384 + kc * 4096 + offB);
            #pragma unroll
            for (int mt = 0; mt < 2; mt++) {
                mma_bf16(acc[mt], qf[0][kc][mt], b0h, b1h);
                mma_bf16(acc[mt], qf[0][kc][mt], b0l, b1l);
                mma_bf16(acc[mt], qf[1][kc][mt], b0h, b1h);
            }
        }
        #pragma unroll
        for (int mt = 0; mt < 2; mt++) {
            int r = mt * 16 + gr;
            int c = it * 128 + n0 + gc;
            unsigned pc0 = (unsigned)c ^ ((unsigned)(r & 7) << 2);
            unsigned pc1 = (unsigned)c ^ ((unsigned)((r + 8) & 7) << 2);
            *(float2*)&Ssc[r * 1024 + pc0] = make_float2(acc[mt][0] * 0.125f, acc[mt][1] * 0.125f);
            *(float2*)&Ssc[(r + 8) * 1024 + pc1] = make_float2(acc[mt][2] * 0.125f, acc[mt][3] * 0.125f);
        }
    }

    load_vt512(ring, Vhp, Vlp, 0, tid);
    __syncthreads();
    load_vt512(ring + ABUF, Vhp, Vlp, 1, tid);

    // ---- fused single-pass masked softmax (fixed shift mx=0; exact algebra) ----
    #pragma unroll 1
    for (int rr = 0; rr < 2; rr++) {
        int r = wid * 2 + rr;
        int qg = q0 + r;
        unsigned xr = (unsigned)(r & 7) << 2;
        const unsigned* mb = g_mbits + (size_t)(b * 1024 + qg) * 32;
        float* srow = &Ssc[r * 1024];

        unsigned wv[16];
        #pragma unroll
        for (int i = 0; i < 16; i++) wv[i] = __ldg(&mb[(lane >> 4) + 2 * i]);

        unsigned wl = __ldg(&mb[lane]);
        int pc = __popc(wl);
        #pragma unroll
        for (int o = 16; o; o >>= 1) pc += __shfl_xor_sync(0xffffffffu, pc, o);
        unsigned wdiag = __shfl_sync(0xffffffffu, wl, qg >> 5);
        int cnt = pc + (((wdiag >> (qg & 31)) & 1u) ? 0 : 1);

        // single pass: mask + exp + sum (scores bounded ~|12| -> exp(0-shift) safe)
        float treg[32];
        float sum = 0.f;
        unsigned bp = ((unsigned)lane * 2) & 31;
        #pragma unroll
        for (int i = 0; i < 16; i++) {
            int kk = lane * 2 + 64 * i;
            float2 s = *(float2*)&srow[(unsigned)kk ^ xr];
            bool a0 = (kk != qg) && !((wv[i] >> bp) & 1u);
            bool a1 = (kk + 1 != qg) && !((wv[i] >> (bp + 1)) & 1u);
            float e0 = a0 ? __expf(s.x) : 0.f;
            float e1 = a1 ? __expf(s.y) : 0.f;
            treg[2 * i] = e0; treg[2 * i + 1] = e1;
            sum += e0 + e1;
        }
        #pragma unroll
        for (int o = 16; o; o >>= 1) sum += __shfl_xor_sync(0xffffffffu, sum, o);
        float Z = sum + (float)cnt;           // masked entries contribute exp(0)=1
        float inv = 1.f / (sum + 1e-13f * Z);
        float* orow = attn_out + (((size_t)h * NB + b) * 1024 + qg) * 1024;
        #pragma unroll
        for (int i = 0; i < 16; i++) {
            int kk = lane * 2 + 64 * i;
            float a0 = treg[2 * i] * inv, a1 = treg[2 * i + 1] * inv;
            *(float2*)&orow[kk] = make_float2(a0, a1);
            unsigned slot = (unsigned)((kk >> 3) ^ (r & 7));
            unsigned word = ((unsigned)kk >> 1) & 3;
            *(unsigned*)(smc + (size_t)r * 4096 + (slot << 4) + word * 4) = pack_hi(a0, a1);
            *(unsigned*)(smc + (size_t)r * 4096 + (slot << 4) + word * 4 + 2048) = pack_lo(a0, a1);
        }
    }
    __syncthreads();

    // ---- pass 2: out = P V (wk4 x wn4) ----
    float pacc[2][2][4];
    #pragma unroll
    for (int a = 0; a < 2; a++)
        #pragma unroll
        for (int c = 0; c < 2; c++)
            #pragma unroll
            for (int e = 0; e < 4; e++) pacc[a][c][e] = 0.f;
    int wk = wid >> 2, wn = wid & 3;

    #pragma unroll 1
    for (int kt = 0; kt < 8; kt++) {
        asm volatile("cp.async.wait_group 1;" ::: "memory");
        __syncthreads();
        if (kt + 2 < 8) load_vt512(ring + (unsigned)((kt + 2) % 3) * ABUF, Vhp, Vlp, kt + 2, tid);
        else asm volatile("cp.async.commit_group;");

        unsigned buf = ring + (unsigned)(kt % 3) * ABUF;
        #pragma unroll
        for (int i = 0; i < 2; i++) {
            int s8 = wk * 2 + i;
            int kseg = kt * 8 + s8;
            unsigned pf[2][2][4];
            #pragma unroll
            for (int v = 0; v < 2; v++)
                #pragma unroll
                for (int mt = 0; mt < 2; mt++) {
                    int r = mt * 16 + rA;
                    unsigned slot = (unsigned)((v * 128 + kseg * 2 + chv) ^ (r & 7));
                    ldm4(pf[v][mt][0], pf[v][mt][1], pf[v][mt][2], pf[v][mt][3],
                         sb + r * 4096 + (slot << 4));
                }
            unsigned bh4[4], bl4[4];
            int krow = s8 * 16 + rA;
            unsigned ob = krow * 128 + ((unsigned)((wn * 2 + chv) ^ (krow & 7)) << 4);
            ldm4t(bh4[0], bh4[1], bh4[2], bh4[3], buf + ob);
            ldm4t(bl4[0], bl4[1], bl4[2], bl4[3], buf + 16384 + ob);
            #pragma unroll
            for (int mt = 0; mt < 2; mt++)
                #pragma unroll
                for (int nt = 0; nt < 2; nt++) {
                    mma_bf16(pacc[mt][nt], pf[0][mt], bh4[nt * 2], bh4[nt * 2 + 1]);
                    mma_bf16(pacc[mt][nt], pf[0][mt], bl4[nt * 2], bl4[nt * 2 + 1]);
                    mma_bf16(pacc[mt][nt], pf[1][mt], bh4[nt * 2], bh4[nt * 2 + 1]);
                }
        }
    }
    asm volatile("cp.async.wait_group 0;" ::: "memory");
    __syncthreads();

    float* red = (float*)(smc + AKB);
    if (wk > 0) {
        int base = (wk - 1) * 2048;
        #pragma unroll
        for (int mt = 0; mt < 2; mt++)
            #pragma unroll
            for (int nt = 0; nt < 2; nt++) {
                int rr0 = mt * 16 + gr;
                int cc0 = wn * 16 + nt * 8 + gc;
                red[base + rr0 * 64 + cc0]     = pacc[mt][nt][0];
                red[base + rr0 * 64 + cc0 + 1] = pacc[mt][nt][1];
                red[base + (rr0 + 8) * 64 + cc0]     = pacc[mt][nt][2];
                red[base + (rr0 + 8) * 64 + cc0 + 1] = pacc[mt][nt][3];
            }
    }
    __syncthreads();
    if (wk == 0) {
        #pragma unroll
        for (int mt = 0; mt < 2; mt++)
            #pragma unroll
            for (int nt = 0; nt < 2; nt++) {
                int rr0 = mt * 16 + gr;
                int cc0 = wn * 16 + nt * 8 + gc;
                float v0 = pacc[mt][nt][0], v1 = pacc[mt][nt][1];
                float v2 = pacc[mt][nt][2], v3 = pacc[mt][nt][3];
                #pragma unroll
                for (int g = 0; g < 3; g++) {
                    v0 += red[g * 2048 + rr0 * 64 + cc0];
                    v1 += red[g * 2048 + rr0 * 64 + cc0 + 1];
                    v2 += red[g * 2048 + (rr0 + 8) * 64 + cc0];
                    v3 += red[g * 2048 + (rr0 + 8) * 64 + cc0 + 1];
                }
                size_t p0 = ((size_t)b * 1024 + q0 + rr0) * 512 + h * 64 + cc0;
                size_t p1 = p0 + 8 * 512;
                store_hl2(&g_atth[p0], &g_attl[p0], v0, v1);
                store_hl2(&g_atth[p1], &g_attl[p1], v2, v3);
            }
    }
}

// ---------------- launch ----------------
extern "C" void kernel_launch(void* const* d_in, const int* in_sizes, int n_in,
                              void* d_out, int out_size)
{
    (void)in_sizes; (void)n_in; (void)out_size;
    const float* q   = (const float*)d_in[0];
    const float* k   = (const float*)d_in[1];
    const float* v   = (const float*)d_in[2];
    const int*   msk = (const int*)d_in[3];
    const float* Wq  = (const float*)d_in[4];
    const float* Wk  = (const float*)d_in[5];
    const float* Wv  = (const float*)d_in[6];
    const float* Wfc = (const float*)d_in[7];
    const float* g1  = (const float*)d_in[8];
    const float* b1  = (const float*)d_in[9];
    const float* g2  = (const float*)d_in[10];
    const float* b2  = (const float*)d_in[11];
    const float* g3  = (const float*)d_in[12];
    const float* b3  = (const float*)d_in[13];

    float* out = (float*)d_out;
    float* dyn_out  = out;                            // [16,1024,512]
    float* attn_out = out + (size_t)MROWS * 512;      // [128,1024,1024]

    const int gemm_smem = 4 * STG;                    // 98304 B -> 2 CTAs/SM
    const int attn_smem = 131072 + 3 * 32768;         // 229376 B
    cudaFuncSetAttribute(gemm_mma_kernel, cudaFuncAttributeMaxDynamicSharedMemorySize, gemm_smem);
    cudaFuncSetAttribute(attn_mma_kernel, cudaFuncAttributeMaxDynamicSharedMemorySize, attn_smem);

    prep_kernel<<<9216, 256>>>(msk, q, k, v, g1, b1, g2, b2, g3, b3, Wq, Wk, Wv, Wfc);
    gemm_mma_kernel<<<dim3(8, 128, 3), 256, gemm_smem>>>(nullptr, 0);   // Q,K,V projections
    attn_mma_kernel<<<dim3(32, 128), 512, attn_smem>>>(msk, attn_out);
    gemm_mma_kernel<<<dim3(8, 128, 1), 256, gemm_smem>>>(dyn_out, 1);   // fc
}

// round 17
// speedup vs baseline: 1.5973x; 1.0105x over previous
#include <cuda_runtime.h>
#include <cuda_bf16.h>

#define NB 16
#define NL 1024
#define NH 8
#define MROWS (NB*NL)

// ---------------- scratch ----------------
__device__ __align__(16) __nv_bfloat16 g_Qh[NB*NH*NL*64];
__device__ __align__(16) __nv_bfloat16 g_Ql[NB*NH*NL*64];
__device__ __align__(16) __nv_bfloat16 g_Kh[NB*NH*NL*64];
__device__ __align__(16) __nv_bfloat16 g_Kl[NB*NH*NL*64];
__device__ __align__(16) __nv_bfloat16 g_Vh[NB*NH*NL*64];
__device__ __align__(16) __nv_bfloat16 g_Vl[NB*NH*NL*64];
__device__ __align__(16) __nv_bfloat16 g_Ah[3][MROWS*512];
__device__ __align__(16) __nv_bfloat16 g_Al[3][MROWS*512];
__device__ __align__(16) __nv_bfloat16 g_Wh[4][512*512];
__device__ __align__(16) __nv_bfloat16 g_Wl[4][512*512];
__device__ __align__(16) __nv_bfloat16 g_atth[MROWS*512];
__device__ __align__(16) __nv_bfloat16 g_attl[MROWS*512];
__device__ __align__(16) unsigned g_mbits[NB*NL*32];   // 2MB packed mask bits

// ---------------- helpers ----------------
__device__ __forceinline__ unsigned smem_u32(const void* p) {
    unsigned a;
    asm("{ .reg .u64 t; cvta.to.shared.u64 t, %1; cvt.u32.u64 %0, t; }" : "=r"(a) : "l"(p));
    return a;
}
__device__ __forceinline__ void cp16(unsigned dst, const void* src) {
    asm volatile("cp.async.cg.shared.global [%0], [%1], 16;" :: "r"(dst), "l"(src));
}
__device__ __forceinline__ void ldm4(unsigned& r0, unsigned& r1, unsigned& r2, unsigned& r3, unsigned a) {
    asm volatile("ldmatrix.sync.aligned.m8n8.x4.shared.b16 {%0,%1,%2,%3}, [%4];"
                 : "=r"(r0), "=r"(r1), "=r"(r2), "=r"(r3) : "r"(a));
}
__device__ __forceinline__ void ldm2(unsigned& r0, unsigned& r1, unsigned a) {
    asm volatile("ldmatrix.sync.aligned.m8n8.x2.shared.b16 {%0,%1}, [%2];"
                 : "=r"(r0), "=r"(r1) : "r"(a));
}
__device__ __forceinline__ void ldm4t(unsigned& r0, unsigned& r1, unsigned& r2, unsigned& r3, unsigned a) {
    asm volatile("ldmatrix.sync.aligned.m8n8.x4.trans.shared.b16 {%0,%1,%2,%3}, [%4];"
                 : "=r"(r0), "=r"(r1), "=r"(r2), "=r"(r3) : "r"(a));
}
__device__ __forceinline__ void mma_bf16(float* d, const unsigned* a, unsigned b0, unsigned b1) {
    asm volatile(
        "mma.sync.aligned.m16n8k16.row.col.f32.bf16.bf16.f32 "
        "{%0,%1,%2,%3}, {%4,%5,%6,%7}, {%8,%9}, {%0,%1,%2,%3};"
        : "+f"(d[0]), "+f"(d[1]), "+f"(d[2]), "+f"(d[3])
        : "r"(a[0]), "r"(a[1]), "r"(a[2]), "r"(a[3]), "r"(b0), "r"(b1));
}
__device__ __forceinline__ void split_hl(float y, __nv_bfloat16& h, __nv_bfloat16& l) {
    h = __float2bfloat16(y);
    l = __float2bfloat16(y - __bfloat162float(h));
}
__device__ __forceinline__ void store_hl2(__nv_bfloat16* ph, __nv_bfloat16* pl, float a, float b) {
    __nv_bfloat162 H, L;
    split_hl(a, H.x, L.x);
    split_hl(b, H.y, L.y);
    *(__nv_bfloat162*)ph = H;
    *(__nv_bfloat162*)pl = L;
}
__device__ __forceinline__ unsigned pack_hi(float a, float b) {
    __nv_bfloat162 H; H.x = __float2bfloat16(a); H.y = __float2bfloat16(b);
    return *(unsigned*)&H;
}
__device__ __forceinline__ unsigned pack_lo(float a, float b) {
    __nv_bfloat16 ha = __float2bfloat16(a), hb = __float2bfloat16(b);
    __nv_bfloat162 L;
    L.x = __float2bfloat16(a - __bfloat162float(ha));
    L.y = __float2bfloat16(b - __bfloat162float(hb));
    return *(unsigned*)&L;
}

// ---------------- prep: LN+split | W split (mask pack moved into proj launch) ----------------
__global__ __launch_bounds__(256) void prep_kernel(
    const float* __restrict__ q, const float* __restrict__ k, const float* __restrict__ v,
    const float* __restrict__ g1, const float* __restrict__ b1,
    const float* __restrict__ g2, const float* __restrict__ b2,
    const float* __restrict__ g3, const float* __restrict__ b3,
    const float* __restrict__ Wq, const float* __restrict__ Wk,
    const float* __restrict__ Wv, const float* __restrict__ Wfc)
{
    int bx = blockIdx.x;
    int warp = threadIdx.x >> 5, lane = threadIdx.x & 31;

    if (bx < 6144) {
        int t = bx >> 11;
        int row = (bx & 2047) * 8 + warp;
        const float* x  = (t == 0 ? q  : (t == 1 ? k  : v))  + (size_t)row * 512;
        const float* G  = (t == 0 ? g1 : (t == 1 ? g2 : g3));
        const float* Bt = (t == 0 ? b1 : (t == 1 ? b2 : b3));

        float4 xv[4];
        float s = 0.f, ss = 0.f;
        #pragma unroll
        for (int i = 0; i < 4; i++) {
            xv[i] = ((const float4*)x)[lane + 32 * i];
            s  += xv[i].x + xv[i].y + xv[i].z + xv[i].w;
            ss += xv[i].x*xv[i].x + xv[i].y*xv[i].y + xv[i].z*xv[i].z + xv[i].w*xv[i].w;
        }
        #pragma unroll
        for (int o = 16; o; o >>= 1) {
            s  += __shfl_xor_sync(0xffffffffu, s, o);
            ss += __shfl_xor_sync(0xffffffffu, ss, o);
        }
        float mu = s * (1.f / 512.f);
        float var = ss * (1.f / 512.f) - mu * mu;
        float rs = rsqrtf(var + 1e-5f);

        __nv_bfloat16* ph = g_Ah[t] + (size_t)row * 512;
        __nv_bfloat16* pl = g_Al[t] + (size_t)row * 512;
        #pragma unroll
        for (int i = 0; i < 4; i++) {
            int c4 = lane + 32 * i;
            float4 gv = ((const float4*)G)[c4];
            float4 bv = ((const float4*)Bt)[c4];
            float y[4];
            y[0] = (xv[i].x - mu) * rs * gv.x + bv.x;
            y[1] = (xv[i].y - mu) * rs * gv.y + bv.y;
            y[2] = (xv[i].z - mu) * rs * gv.z + bv.z;
            y[3] = (xv[i].w - mu) * rs * gv.w + bv.w;
            __nv_bfloat16 hh[4], ll[4];
            #pragma unroll
            for (int j = 0; j < 4; j++) split_hl(y[j], hh[j], ll[j]);
            *(uint2*)(ph + c4 * 4) = *(uint2*)hh;
            *(uint2*)(pl + c4 * 4) = *(uint2*)ll;
        }
        return;
    }
    {
        int idx = ((bx - 6144) * 256 + threadIdx.x) * 4;
        int mat = idx >> 18;
        int off = idx & 262143;
        const float* W = (mat == 0) ? Wq : ((mat == 1) ? Wk : ((mat == 2) ? Wv : Wfc));
        float4 xv = *(const float4*)(W + off);
        float y[4] = {xv.x, xv.y, xv.z, xv.w};
        __nv_bfloat16 hh[4], ll[4];
        #pragma unroll
        for (int j = 0; j < 4; j++) split_hl(y[j], hh[j], ll[j]);
        *(uint2*)(g_Wh[mat] + off) = *(uint2*)hh;
        *(uint2*)(g_Wl[mat] + off) = *(uint2*)ll;
    }
}

// ---------------- mma.sync GEMM (R13/R14, validated) + mask-pack rider (z==3) ----------------
#define STG 24576
#define VOFF_AL 8192
#define VOFF_BH 16384
#define VOFF_BL 20480

__device__ __forceinline__ void load_stage_mma(
    const __nv_bfloat16* __restrict__ Ah, const __nv_bfloat16* __restrict__ Al,
    const __nv_bfloat16* __restrict__ Bh, const __nv_bfloat16* __restrict__ Bl,
    int mr0, int nr0, int kb, unsigned dstb, int tid)
{
    {
        int m = tid >> 1, c = tid & 1;
        unsigned sw = (unsigned)(c ^ ((m >> 2) & 1)) << 4;
        #pragma unroll
        for (int kc = 0; kc < 2; kc++) {
            unsigned dst = dstb + kc * 4096 + m * 32 + sw;
            size_t ga = (size_t)(mr0 + m) * 512 + kb + kc * 16 + c * 8;
            cp16(dst,           Ah + ga);
            cp16(dst + VOFF_AL, Al + ga);
        }
    }
    {
        int m = tid >> 2, kc = (tid >> 1) & 1, c = tid & 1;
        unsigned sw = (unsigned)(c ^ ((m >> 2) & 1)) << 4;
        unsigned dst = dstb + VOFF_BH + kc * 2048 + m * 32 + sw;
        size_t gb = (size_t)(nr0 + m) * 512 + kb + kc * 16 + c * 8;
        cp16(dst,                       Bh + gb);
        cp16(dst + (VOFF_BL - VOFF_BH), Bl + gb);
    }
    asm volatile("cp.async.commit_group;");
}

__global__ __launch_bounds__(256, 2) void gemm_mma_kernel(
    float* __restrict__ c_fc, int mode, const int* __restrict__ mask)
{
    // mask-pack rider blocks (projections launch only): z == 3
    if (mode == 0 && blockIdx.z == 3) {
        int idx = blockIdx.y * 8 + blockIdx.x;     // 0..1023
        int warp = threadIdx.x >> 5, lane = threadIdx.x & 31;
        int row0 = idx * 16 + warp * 2;
        #pragma unroll
        for (int rr = 0; rr < 2; rr++) {
            int row = row0 + rr;
            const int* mrow = mask + (size_t)row * 1024;
            #pragma unroll
            for (int j = 0; j < 32; j++) {
                int mv = mrow[j * 32 + lane];
                unsigned w = __ballot_sync(0xffffffffu, mv != 0);
                if (lane == 0) g_mbits[row * 32 + j] = w;
            }
        }
        return;
    }

    extern __shared__ char smem[];
    unsigned sb = smem_u32(smem);
    int tid = threadIdx.x, wid = tid >> 5, lane = tid & 31;
    int z = blockIdx.z;
    int mr0 = blockIdx.y * 128;
    int nr0 = blockIdx.x * 64;

    const __nv_bfloat16 *Ah, *Al, *Wh, *Wl;
    __nv_bfloat16 *oh = 0, *ol = 0;
    if (mode == 0) {
        Ah = g_Ah[z]; Al = g_Al[z]; Wh = g_Wh[z]; Wl = g_Wl[z];
        oh = (z == 0) ? g_Qh : ((z == 1) ? g_Kh : g_Vh);
        ol = (z == 0) ? g_Ql : ((z == 1) ? g_Kl : g_Vl);
    } else {
        Ah = g_atth; Al = g_attl; Wh = g_Wh[3]; Wl = g_Wl[3];
    }

    int rA = lane & 15, chv = lane >> 4;
    unsigned offT = (unsigned)(rA * 32 + ((chv ^ ((rA >> 2) & 1)) << 4));
    int wm = wid >> 1, wn = wid & 1;

    float acc[2][4][4];
    #pragma unroll
    for (int a = 0; a < 2; a++)
        #pragma unroll
        for (int b = 0; b < 4; b++)
            #pragma unroll
            for (int c = 0; c < 4; c++) acc[a][b][c] = 0.f;

    load_stage_mma(Ah, Al, Wh, Wl, mr0, nr0, 0,  sb,           tid);
    load_stage_mma(Ah, Al, Wh, Wl, mr0, nr0, 32, sb + STG,     tid);
    load_stage_mma(Ah, Al, Wh, Wl, mr0, nr0, 64, sb + 2 * STG, tid);

    #pragma unroll 1
    for (int s = 0; s < 16; s++) {
        if (s < 14) { asm volatile("cp.async.wait_group 2;"); }
        else        { asm volatile("cp.async.wait_group 0;"); }
        __syncthreads();
        if (s + 3 < 16)
            load_stage_mma(Ah, Al, Wh, Wl, mr0, nr0, (s + 3) * 32, sb + (unsigned)((s + 3) & 3) * STG, tid);
        unsigned buf = sb + (unsigned)(s & 3) * STG;

        #pragma unroll
        for (int kc = 0; kc < 2; kc++) {
            unsigned abase  = buf + kc * 4096;
            unsigned bbaseh = buf + VOFF_BH + kc * 2048;
            unsigned bbasel = buf + VOFF_BL + kc * 2048;
            unsigned aH[2][4], bH[2][4];
            #pragma unroll
            for (int mt = 0; mt < 2; mt++)
                ldm4(aH[mt][0], aH[mt][1], aH[mt][2], aH[mt][3],
                     abase + (unsigned)((wm * 32 + mt * 16) * 32) + offT);
            #pragma unroll
            for (int bt = 0; bt < 2; bt++)
                ldm4(bH[bt][0], bH[bt][1], bH[bt][2], bH[bt][3],
                     bbaseh + (unsigned)((wn * 32 + bt * 16) * 32) + offT);
            #pragma unroll
            for (int mt = 0; mt < 2; mt++)
                #pragma unroll
                for (int nt = 0; nt < 4; nt++)
                    mma_bf16(acc[mt][nt], aH[mt], bH[nt >> 1][nt & 1], bH[nt >> 1][(nt & 1) + 2]);
            {
                unsigned bL[2][4];
                #pragma unroll
                for (int bt = 0; bt < 2; bt++)
                    ldm4(bL[bt][0], bL[bt][1], bL[bt][2], bL[bt][3],
                         bbasel + (unsigned)((wn * 32 + bt * 16) * 32) + offT);
                #pragma unroll
                for (int mt = 0; mt < 2; mt++)
                    #pragma unroll
                    for (int nt = 0; nt < 4; nt++)
                        mma_bf16(acc[mt][nt], aH[mt], bL[nt >> 1][nt & 1], bL[nt >> 1][(nt & 1) + 2]);
            }
            {
                unsigned aL[2][4];
                #pragma unroll
                for (int mt = 0; mt < 2; mt++)
                    ldm4(aL[mt][0], aL[mt][1], aL[mt][2], aL[mt][3],
                         abase + VOFF_AL + (unsigned)((wm * 32 + mt * 16) * 32) + offT);
                #pragma unroll
                for (int mt = 0; mt < 2; mt++)
                    #pragma unroll
                    for (int nt = 0; nt < 4; nt++)
                        mma_bf16(acc[mt][nt], aL[mt], bH[nt >> 1][nt & 1], bH[nt >> 1][(nt & 1) + 2]);
            }
        }
    }

    int gr = lane >> 2, gc = (lane & 3) * 2;
    #pragma unroll
    for (int mt = 0; mt < 2; mt++) {
        #pragma unroll
        for (int nt = 0; nt < 4; nt++) {
            int r0 = mr0 + wm * 32 + mt * 16 + gr;
            int n0 = nr0 + wn * 32 + nt * 8 + gc;
            if (mode == 0) {
                int h = n0 >> 6, d = n0 & 63;
                int r1 = r0 + 8;
                size_t p0 = ((size_t)((r0 >> 10) * 8 + h) << 16) + (size_t)(r0 & 1023) * 64 + d;
                size_t p1 = ((size_t)((r1 >> 10) * 8 + h) << 16) + (size_t)(r1 & 1023) * 64 + d;
                store_hl2(oh + p0, ol + p0, acc[mt][nt][0], acc[mt][nt][1]);
                store_hl2(oh + p1, ol + p1, acc[mt][nt][2], acc[mt][nt][3]);
            } else {
                float* p0 = c_fc + (size_t)r0 * 512 + n0;
                *(float2*)p0 = make_float2(acc[mt][nt][0], acc[mt][nt][1]);
                *(float2*)(p0 + 8 * 512) = make_float2(acc[mt][nt][2], acc[mt][nt][3]);
            }
        }
    }
}

// ---------------- tensor-core fused attention (verbatim R15 - validated 1014us) ----------------
#define AKB 131072u
#define ABUF 32768u

__device__ __forceinline__ void load_kt512(unsigned buf, const __nv_bfloat16* Kh,
                                           const __nv_bfloat16* Kl, int it, int tid)
{
    #pragma unroll
    for (int i = 0; i < 4; i++) {
        int idx = i * 512 + tid;
        int ver = idx >> 10, g = idx & 1023;
        int row = g >> 3, cc = g & 7;
        int kc = cc >> 1, ch = cc & 1;
        unsigned dst = buf + ver * 16384 + kc * 4096 + row * 32
                     + ((unsigned)(ch ^ ((row >> 2) & 1)) << 4);
        cp16(dst, (ver ? Kl : Kh) + (size_t)(it * 128 + row) * 64 + cc * 8);
    }
    asm volatile("cp.async.commit_group;");
}
__device__ __forceinline__ void load_vt512(unsigned buf, const __nv_bfloat16* Vh,
                                           const __nv_bfloat16* Vl, int it, int tid)
{
    #pragma unroll
    for (int i = 0; i < 4; i++) {
        int idx = i * 512 + tid;
        int ver = idx >> 10, g = idx & 1023;
        int row = g >> 3, cc = g & 7;
        unsigned dst = buf + ver * 16384 + row * 128 + ((unsigned)(cc ^ (row & 7)) << 4);
        cp16(dst, (ver ? Vl : Vh) + (size_t)(it * 128 + row) * 64 + cc * 8);
    }
    asm volatile("cp.async.commit_group;");
}

__global__ __launch_bounds__(512, 1) void attn_mma_kernel(
    const int* __restrict__ mask, float* __restrict__ attn_out)
{
    (void)mask;
    extern __shared__ char smc[];
    unsigned sb = smem_u32(smc);
    float* Ssc = (float*)smc;
    int tid = threadIdx.x, wid = tid >> 5, lane = tid & 31;
    int rA = lane & 15, chv = lane >> 4;
    int gr = lane >> 2, gc = (lane & 3) * 2;
    int q0 = blockIdx.x * 32;
    int bh = blockIdx.y;
    int b = bh >> 3, h = bh & 7;
    const __nv_bfloat16* Qhp = g_Qh + ((size_t)bh << 16) + (size_t)q0 * 64;
    const __nv_bfloat16* Qlp = g_Ql + ((size_t)bh << 16) + (size_t)q0 * 64;
    const __nv_bfloat16* Khp = g_Kh + ((size_t)bh << 16);
    const __nv_bfloat16* Klp = g_Kl + ((size_t)bh << 16);
    const __nv_bfloat16* Vhp = g_Vh + ((size_t)bh << 16);
    const __nv_bfloat16* Vlp = g_Vl + ((size_t)bh << 16);
    unsigned ring = sb + AKB;
    unsigned qarea = ring + 2 * ABUF;

    {
        int ver = tid >> 8, rest = tid & 255;
        int row = rest >> 3, cc = rest & 7;
        int kc = cc >> 1, ch = cc & 1;
        unsigned dst = qarea + ver * 4096 + kc * 1024 + row * 32
                     + ((unsigned)(ch ^ ((row >> 2) & 1)) << 4);
        cp16(dst, (ver ? Qlp : Qhp) + row * 64 + cc * 8);
    }
    load_kt512(ring, Khp, Klp, 0, tid);
    load_kt512(ring + ABUF, Khp, Klp, 1, tid);

    unsigned qf[2][4][2][4];
    int n0 = wid * 8;
    unsigned offAq[2];
    #pragma unroll
    for (int mt = 0; mt < 2; mt++) {
        int r = mt * 16 + rA;
        offAq[mt] = r * 32 + ((unsigned)(chv ^ ((r >> 2) & 1)) << 4);
    }
    int rB = n0 + (lane & 7);
    int chB = (lane >> 3) & 1;
    unsigned offB = rB * 32 + ((unsigned)(chB ^ ((rB >> 2) & 1)) << 4);

    #pragma unroll 1
    for (int it = 0; it < 8; it++) {
        asm volatile("cp.async.wait_group 1;" ::: "memory");
        __syncthreads();
        if (it == 0) {
            #pragma unroll
            for (int v = 0; v < 2; v++)
                #pragma unroll
                for (int kc = 0; kc < 4; kc++)
                    #pragma unroll
                    for (int mt = 0; mt < 2; mt++)
                        ldm4(qf[v][kc][mt][0], qf[v][kc][mt][1], qf[v][kc][mt][2], qf[v][kc][mt][3],
                             qarea + v * 4096 + kc * 1024 + offAq[mt]);
            __syncthreads();
        }
        if (it + 2 < 8) load_kt512(ring + (unsigned)((it + 2) % 3) * ABUF, Khp, Klp, it + 2, tid);
        else asm volatile("cp.async.commit_group;");

        unsigned buf = ring + (unsigned)(it % 3) * ABUF;
        float acc[2][4];
        #pragma unroll
        for (int a = 0; a < 2; a++)
            #pragma unroll
            for (int e = 0; e < 4; e++) acc[a][e] = 0.f;
        #pragma unroll
        for (int kc = 0; kc < 4; kc++) {
            unsigned b0h, b1h, b0l, b1l;
            ldm2(b0h, b1h, buf + kc * 4096 + offB);
            ldm2(b0l, b1l, buf + 16384 + kc * 4096 + offB);
            #pragma unroll
            for (int mt = 0; mt < 2; mt++) {
                mma_bf16(acc[mt], qf[0][kc][mt], b0h, b1h);
                mma_bf16(acc[mt], qf[0][kc][mt], b0l, b1l);
                mma_bf16(acc[mt], qf[1][kc][mt], b0h, b1h);
            }
        }
        #pragma unroll
        for (int mt = 0; mt < 2; mt++) {
            int r = mt * 16 + gr;
            int c = it * 128 + n0 + gc;
            unsigned pc0 = (unsigned)c ^ ((unsigned)(r & 7) << 2);
            unsigned pc1 = (unsigned)c ^ ((unsigned)((r + 8) & 7) << 2);
            *(float2*)&Ssc[r * 1024 + pc0] = make_float2(acc[mt][0] * 0.125f, acc[mt][1] * 0.125f);
            *(float2*)&Ssc[(r + 8) * 1024 + pc1] = make_float2(acc[mt][2] * 0.125f, acc[mt][3] * 0.125f);
        }
    }

    load_vt512(ring, Vhp, Vlp, 0, tid);
    __syncthreads();
    load_vt512(ring + ABUF, Vhp, Vlp, 1, tid);

    // ---- fused single-pass masked softmax (fixed shift; exact algebra) ----
    #pragma unroll 1
    for (int rr = 0; rr < 2; rr++) {
        int r = wid * 2 + rr;
        int qg = q0 + r;
        unsigned xr = (unsigned)(r & 7) << 2;
        const unsigned* mb = g_mbits + (size_t)(b * 1024 + qg) * 32;
        float* srow = &Ssc[r * 1024];

        unsigned wv[16];
        #pragma unroll
        for (int i = 0; i < 16; i++) wv[i] = __ldg(&mb[(lane >> 4) + 2 * i]);

        unsigned wl = __ldg(&mb[lane]);
        int pc = __popc(wl);
        #pragma unroll
        for (int o = 16; o; o >>= 1) pc += __shfl_xor_sync(0xffffffffu, pc, o);
        unsigned wdiag = __shfl_sync(0xffffffffu, wl, qg >> 5);
        int cnt = pc + (((wdiag >> (qg & 31)) & 1u) ? 0 : 1);

        float treg[32];
        float sum = 0.f;
        unsigned bp = ((unsigned)lane * 2) & 31;
        #pragma unroll
        for (int i = 0; i < 16; i++) {
            int kk = lane * 2 + 64 * i;
            float2 s = *(float2*)&srow[(unsigned)kk ^ xr];
            bool a0 = (kk != qg) && !((wv[i] >> bp) & 1u);
            bool a1 = (kk + 1 != qg) && !((wv[i] >> (bp + 1)) & 1u);
            float e0 = a0 ? __expf(s.x) : 0.f;
            float e1 = a1 ? __expf(s.y) : 0.f;
            treg[2 * i] = e0; treg[2 * i + 1] = e1;
            sum += e0 + e1;
        }
        #pragma unroll
        for (int o = 16; o; o >>= 1) sum += __shfl_xor_sync(0xffffffffu, sum, o);
        float Z = sum + (float)cnt;
        float inv = 1.f / (sum + 1e-13f * Z);
        float* orow = attn_out + (((size_t)h * NB + b) * 1024 + qg) * 1024;
        #pragma unroll
        for (int i = 0; i < 16; i++) {
            int kk = lane * 2 + 64 * i;
            float a0 = treg[2 * i] * inv, a1 = treg[2 * i + 1] * inv;
            *(float2*)&orow[kk] = make_float2(a0, a1);
            unsigned slot = (unsigned)((kk >> 3) ^ (r & 7));
            unsigned word = ((unsigned)kk >> 1) & 3;
            *(unsigned*)(smc + (size_t)r * 4096 + (slot << 4) + word * 4) = pack_hi(a0, a1);
            *(unsigned*)(smc + (size_t)r * 4096 + (slot << 4) + word * 4 + 2048) = pack_lo(a0, a1);
        }
    }
    __syncthreads();

    // ---- pass 2: out = P V (wk4 x wn4) ----
    float pacc[2][2][4];
    #pragma unroll
    for (int a = 0; a < 2; a++)
        #pragma unroll
        for (int c = 0; c < 2; c++)
            #pragma unroll
            for (int e = 0; e < 4; e++) pacc[a][c][e] = 0.f;
    int wk = wid >> 2, wn = wid & 3;

    #pragma unroll 1
    for (int kt = 0; kt < 8; kt++) {
        asm volatile("cp.async.wait_group 1;" ::: "memory");
        __syncthreads();
        if (kt + 2 < 8) load_vt512(ring + (unsigned)((kt + 2) % 3) * ABUF, Vhp, Vlp, kt + 2, tid);
        else asm volatile("cp.async.commit_group;");

        unsigned buf = ring + (unsigned)(kt % 3) * ABUF;
        #pragma unroll
        for (int i = 0; i < 2; i++) {
            int s8 = wk * 2 + i;
            int kseg = kt * 8 + s8;
            unsigned pf[2][2][4];
            #pragma unroll
            for (int v = 0; v < 2; v++)
                #pragma unroll
                for (int mt = 0; mt < 2; mt++) {
                    int r = mt * 16 + rA;
                    unsigned slot = (unsigned)((v * 128 + kseg * 2 + chv) ^ (r & 7));
                    ldm4(pf[v][mt][0], pf[v][mt][1], pf[v][mt][2], pf[v][mt][3],
                         sb + r * 4096 + (slot << 4));
                }
            unsigned bh4[4], bl4[4];
            int krow = s8 * 16 + rA;
            unsigned ob = krow * 128 + ((unsigned)((wn * 2 + chv) ^ (krow & 7)) << 4);
            ldm4t(bh4[0], bh4[1], bh4[2], bh4[3], buf + ob);
            ldm4t(bl4[0], bl4[1], bl4[2], bl4[3], buf + 16384 + ob);
            #pragma unroll
            for (int mt = 0; mt < 2; mt++)
                #pragma unroll
                for (int nt = 0; nt < 2; nt++) {
                    mma_bf16(pacc[mt][nt], pf[0][mt], bh4[nt * 2], bh4[nt * 2 + 1]);
                    mma_bf16(pacc[mt][nt], pf[0][mt], bl4[nt * 2], bl4[nt * 2 + 1]);
                    mma_bf16(pacc[mt][nt], pf[1][mt], bh4[nt * 2], bh4[nt * 2 + 1]);
                }
        }
    }
    asm volatile("cp.async.wait_group 0;" ::: "memory");
    __syncthreads();

    float* red = (float*)(smc + AKB);
    if (wk > 0) {
        int base = (wk - 1) * 2048;
        #pragma unroll
        for (int mt = 0; mt < 2; mt++)
            #pragma unroll
            for (int nt = 0; nt < 2; nt++) {
                int rr0 = mt * 16 + gr;
                int cc0 = wn * 16 + nt * 8 + gc;
                red[base + rr0 * 64 + cc0]     = pacc[mt][nt][0];
                red[base + rr0 * 64 + cc0 + 1] = pacc[mt][nt][1];
                red[base + (rr0 + 8) * 64 + cc0]     = pacc[mt][nt][2];
                red[base + (rr0 + 8) * 64 + cc0 + 1] = pacc[mt][nt][3];
            }
    }
    __syncthreads();
    if (wk == 0) {
        #pragma unroll
        for (int mt = 0; mt < 2; mt++)
            #pragma unroll
            for (int nt = 0; nt < 2; nt++) {
                int rr0 = mt * 16 + gr;
                int cc0 = wn * 16 + nt * 8 + gc;
                float v0 = pacc[mt][nt][0], v1 = pacc[mt][nt][1];
                float v2 = pacc[mt][nt][2], v3 = pacc[mt][nt][3];
                #pragma unroll
                for (int g = 0; g < 3; g++) {
                    v0 += red[g * 2048 + rr0 * 64 + cc0];
                    v1 += red[g * 2048 + rr0 * 64 + cc0 + 1];
                    v2 += red[g * 2048 + (rr0 + 8) * 64 + cc0];
                    v3 += red[g * 2048 + (rr0 + 8) * 64 + cc0 + 1];
                }
                size_t p0 = ((size_t)b * 1024 + q0 + rr0) * 512 + h * 64 + cc0;
                size_t p1 = p0 + 8 * 512;
                store_hl2(&g_atth[p0], &g_attl[p0], v0, v1);
                store_hl2(&g_atth[p1], &g_attl[p1], v2, v3);
            }
    }
}

// ---------------- launch ----------------
extern "C" void kernel_launch(void* const* d_in, const int* in_sizes, int n_in,
                              void* d_out, int out_size)
{
    (void)in_sizes; (void)n_in; (void)out_size;
    const float* q   = (const float*)d_in[0];
    const float* k   = (const float*)d_in[1];
    const float* v   = (const float*)d_in[2];
    const int*   msk = (const int*)d_in[3];
    const float* Wq  = (const float*)d_in[4];
    const float* Wk  = (const float*)d_in[5];
    const float* Wv  = (const float*)d_in[6];
    const float* Wfc = (const float*)d_in[7];
    const float* g1  = (const float*)d_in[8];
    const float* b1  = (const float*)d_in[9];
    const float* g2  = (const float*)d_in[10];
    const float* b2  = (const float*)d_in[11];
    const float* g3  = (const float*)d_in[12];
    const float* b3  = (const float*)d_in[13];

    float* out = (float*)d_out;
    float* dyn_out  = out;                            // [16,1024,512]
    float* attn_out = out + (size_t)MROWS * 512;      // [128,1024,1024]

    const int gemm_smem = 4 * STG;                    // 98304 B -> 2 CTAs/SM
    const int attn_smem = 131072 + 3 * 32768;         // 229376 B
    cudaFuncSetAttribute(gemm_mma_kernel, cudaFuncAttributeMaxDynamicSharedMemorySize, gemm_smem);
    cudaFuncSetAttribute(attn_mma_kernel, cudaFuncAttributeMaxDynamicSharedMemorySize, attn_smem);

    prep_kernel<<<7168, 256>>>(q, k, v, g1, b1, g2, b2, g3, b3, Wq, Wk, Wv, Wfc);
    gemm_mma_kernel<<<dim3(8, 128, 4), 256, gemm_smem>>>(nullptr, 0, msk);  // Q,K,V proj + mask pack
    attn_mma_kernel<<<dim3(32, 128), 512, attn_smem>>>(msk, attn_out);
    gemm_mma_kernel<<<dim3(8, 128, 1), 256, gemm_smem>>>(dyn_out, 1, msk);  // fc
}